// round 10
// baseline (speedup 1.0000x reference)
#include <cuda_runtime.h>
#include <cuda_fp16.h>
#include <cstdint>

#define NNODES 50000
#define FDIM   256
#define KMIX   5
#define EMAX   1700000

// ---------------- scratch ----------------
__device__ unsigned g_mbits[NNODES * 8];      // bit mask, 256 bits/node
__device__ float g_indeg[NNODES];
__device__ float g_gamma[NNODES * KMIX];
__device__ int   g_flags[2];
__device__ int   g_count[NNODES];
__device__ int   g_cursor[NNODES];
__device__ int   g_offset[NNODES + 1];
__device__ int   g_sorted[EMAX];
__device__ float g_ivar[KMIX * FDIM];         // exp(-logvars)
__device__ float2 g_htab[1025];               // h(w): value, delta-per-interval
__device__ __half g_S0h[NNODES * FDIM];       // fp16 aggregated S0
__device__ __half g_SMh[NNODES * FDIM];       // aggregated mask counts (exact fp16)
// B concat (single fp16): [group g (32 outs)][352 rows (n)][256 (k)]
__device__ __half g_B[8][352 * 256];

// ---------------- PTX helpers (baseline ISA only) ----------------
__device__ __forceinline__ uint32_t smem_u32(const void* p) {
    uint32_t a;
    asm("{ .reg .u64 t; cvta.to.shared.u64 t, %1; cvt.u32.u64 %0, t; }" : "=r"(a) : "l"(p));
    return a;
}
__device__ __forceinline__ void cpasync16(uint32_t dst, const void* src) {
    asm volatile("cp.async.cg.shared.global [%0], [%1], 16;" :: "r"(dst), "l"(src));
}
#define CP_COMMIT() asm volatile("cp.async.commit_group;" ::: "memory")
#define CP_WAIT1()  asm volatile("cp.async.wait_group 1;" ::: "memory")
#define CP_WAIT0()  asm volatile("cp.async.wait_group 0;" ::: "memory")

__device__ __forceinline__ void ldsm4(uint32_t* r, uint32_t addr) {
    asm volatile("ldmatrix.sync.aligned.m8n8.x4.shared.b16 {%0,%1,%2,%3}, [%4];"
                 : "=r"(r[0]), "=r"(r[1]), "=r"(r[2]), "=r"(r[3]) : "r"(addr));
}
__device__ __forceinline__ void mma16816(float* d, const uint32_t* a, const uint32_t* b) {
    asm volatile("mma.sync.aligned.m16n8k16.row.col.f32.f16.f16.f32 "
                 "{%0,%1,%2,%3}, {%4,%5,%6,%7}, {%8,%9}, {%0,%1,%2,%3};"
                 : "+f"(d[0]), "+f"(d[1]), "+f"(d[2]), "+f"(d[3])
                 : "r"(a[0]), "r"(a[1]), "r"(a[2]), "r"(a[3]), "r"(b[0]), "r"(b[1]));
}

// ---------------- fused init: zero + ivar + htab + detect ----------------
__device__ __forceinline__ float h_exact(float w) {
    return 0.3989422804014327f * expf(-0.5f * w * w)
         + 0.5f * w * (1.0f + erff(w * 0.7071067811865476f));
}

__global__ void init_kernel(const void* mask, const void* edges,
                            const float* __restrict__ logvars) {
    int b = blockIdx.x;
    int t = threadIdx.x;
    if (b < 196) {                            // zero counters
        int i = b * 256 + t;
        if (i < NNODES) { g_count[i] = 0; g_cursor[i] = 0; }
    } else if (b < 201) {                     // ivar (1280)
        int i = (b - 196) * 256 + t;
        if (i < KMIX * FDIM) g_ivar[i] = expf(-logvars[i]);
    } else if (b < 206) {                     // htab (1025)
        int i = (b - 201) * 256 + t;
        if (i <= 1024) {
            float w0 = -8.0f + i * (1.0f / 64.0f);
            float h0 = h_exact(w0);
            float h1 = h_exact(w0 + (1.0f / 64.0f));
            g_htab[i] = make_float2(h0, h1 - h0);
        }
    } else {                                  // detect dtypes
        int any_m = 0, any_e = 0;
        const unsigned char* mb = (const unsigned char*)mask;
        const int* ei = (const int*)edges;
        for (int i = t; i < 4096; i += 256) {
            if (mb[4 * i + 1] != 0) any_m = 1;
            if (ei[2 * i + 1] != 0) any_e = 1;
        }
        any_m = __syncthreads_or(any_m);
        any_e = __syncthreads_or(any_e);
        if (t == 0) { g_flags[0] = any_m ? 1 : 0; g_flags[1] = any_e ? 0 : 1; }
    }
}

// ---------------- prep: mask -> mbits only ----------------
__global__ __launch_bounds__(256) void prep_kernel(const void* __restrict__ mask) {
    int n = blockIdx.x;
    int f = threadIdx.x;
    int idx = n * FDIM + f;
    int m = g_flags[0] ? (int)((const unsigned char*)mask)[idx]
                       : ((const int*)mask)[idx];
    unsigned bal = __ballot_sync(0xffffffffu, m);
    if ((f & 31) == 0) g_mbits[n * 8 + (f >> 5)] = bal;
}

// ---------------- CSR build ----------------
__global__ void count_kernel(const void* __restrict__ edges, int E) {
    int i = blockIdx.x * blockDim.x + threadIdx.x;
    if (i >= E) return;
    int dst = g_flags[1] ? (int)((const long long*)edges)[E + i]
                         : ((const int*)edges)[E + i];
    atomicAdd(&g_count[dst], 1);
}

__global__ __launch_bounds__(1024) void scan_kernel() {
    const int SEG = (NNODES + 1023) / 1024;
    int t = threadIdx.x;
    int base = t * SEG;
    int s = 0;
    for (int i = 0; i < SEG; i++) {
        int idx = base + i;
        if (idx < NNODES) s += g_count[idx];
    }
    __shared__ int ss[1024];
    ss[t] = s;
    __syncthreads();
    for (int off = 1; off < 1024; off <<= 1) {
        int v = (t >= off) ? ss[t - off] : 0;
        __syncthreads();
        ss[t] += v;
        __syncthreads();
    }
    int run = ss[t] - s;
    for (int i = 0; i < SEG; i++) {
        int idx = base + i;
        if (idx < NNODES) { g_offset[idx] = run; run += g_count[idx]; }
    }
    if (t == 1023) g_offset[NNODES] = ss[1023];
}

__global__ void scatter_kernel(const void* __restrict__ edges, int E) {
    int i = blockIdx.x * blockDim.x + threadIdx.x;
    if (i >= E) return;
    int src, dst;
    if (g_flags[1]) {
        const long long* e = (const long long*)edges;
        src = (int)e[i]; dst = (int)e[E + i];
    } else {
        const int* e = (const int*)edges;
        src = e[i]; dst = e[E + i];
    }
    int pos = atomicAdd(&g_cursor[dst], 1);
    g_sorted[g_offset[dst] + pos] = src;
}

// ---------------- aggregate: CSR gather -> S0h/SMh + indeg + gamma ------
__global__ __launch_bounds__(256) void aggregate_kernel(
    const float* __restrict__ x, const float* __restrict__ logp,
    const float* __restrict__ means)
{
    int n = blockIdx.x;
    int f = threadIdx.x;
    int wsel = f >> 5, bsel = f & 31;
    int wrp = f >> 5, lane = f & 31;

    int beg = g_offset[n], end = g_offset[n + 1];

    unsigned mb = g_mbits[n * 8 + wsel];
    int bit = (mb >> bsel) & 1;
    float xv = __ldg(&x[(size_t)n * FDIM + f]);
    float accS = bit ? 0.0f : xv;
    int cnt = bit;

    // gamma logits partial (self x only)
    float q[KMIX];
#pragma unroll
    for (int k = 0; k < KMIX; k++) {
        float d = xv - __ldg(&means[k * FDIM + f]);
        float iv = g_ivar[k * FDIM + f];
        q[k] = bit ? 0.0f : d * d * iv;
    }

    __shared__ int ssrc[256];
    for (int chunk = beg; chunk < end; chunk += 256) {
        int nload = min(256, end - chunk);
        __syncthreads();
        if (f < nload) ssrc[f] = g_sorted[chunk + f];
        __syncthreads();
        int i = 0;
        for (; i + 2 <= nload; i += 2) {
            int s0 = ssrc[i], s1 = ssrc[i + 1];
            unsigned m0 = __ldg(&g_mbits[s0 * 8 + wsel]);
            unsigned m1 = __ldg(&g_mbits[s1 * 8 + wsel]);
            float v0 = __ldg(&x[(size_t)s0 * FDIM + f]);
            float v1 = __ldg(&x[(size_t)s1 * FDIM + f]);
            int b0 = (m0 >> bsel) & 1, b1 = (m1 >> bsel) & 1;
            accS += b0 ? 0.0f : v0;
            accS += b1 ? 0.0f : v1;
            cnt += b0 + b1;
        }
        if (i < nload) {
            int s0 = ssrc[i];
            unsigned m0 = __ldg(&g_mbits[s0 * 8 + wsel]);
            float v0 = __ldg(&x[(size_t)s0 * FDIM + f]);
            int b0 = (m0 >> bsel) & 1;
            accS += b0 ? 0.0f : v0;
            cnt += b0;
        }
    }

    int idx = n * FDIM + f;
    g_S0h[idx] = __float2half_rn(accS);
    g_SMh[idx] = __float2half_rn((float)cnt);
    if (f == 0) g_indeg[n] = (float)(end - beg);

    // gamma reduction + softmax
#pragma unroll
    for (int k = 0; k < KMIX; k++)
        for (int off = 16; off; off >>= 1)
            q[k] += __shfl_down_sync(0xffffffffu, q[k], off);
    __shared__ float red[8][KMIX];
    if (lane == 0)
#pragma unroll
        for (int k = 0; k < KMIX; k++) red[wrp][k] = q[k];
    __syncthreads();
    if (f == 0) {
        float l[KMIX], mx = -1e30f;
#pragma unroll
        for (int k = 0; k < KMIX; k++) {
            float s = 0.f;
            for (int ww = 0; ww < 8; ww++) s += red[ww][k];
            l[k] = logp[k] - 0.5f * s;
            mx = fmaxf(mx, l[k]);
        }
        float e[KMIX], se = 0.f;
#pragma unroll
        for (int k = 0; k < KMIX; k++) { e[k] = __expf(l[k] - mx); se += e[k]; }
        float inv = 1.0f / se;
#pragma unroll
        for (int k = 0; k < KMIX; k++) g_gamma[n * KMIX + k] = e[k] * inv;
    }
}

// ---------------- B precompute (n-concat, single fp16) ----------------
__global__ __launch_bounds__(256) void bprep_kernel(
    const float* __restrict__ W, const float* __restrict__ means,
    const float* __restrict__ logvars)
{
    int gidx = blockIdx.x;         // 8*352
    int g = gidx / 352, n = gidx % 352;
    int f = threadIdx.x;
    float val;
    if (n < 32) {
        int o = g * 32 + n;
        val = W[f * FDIM + o];
    } else {
        int mat = (n - 32) >> 5;
        int o = g * 32 + ((n - 32) & 31);
        int k = mat >> 1;
        float w = W[f * FDIM + o];
        if ((mat & 1) == 0) val = means[k * FDIM + f] * w;
        else                val = expf(logvars[k * FDIM + f]) * w * w;
    }
    g_B[g][n * FDIM + f] = __float2half_rn(val);
}

// ---------------- mma.sync GEMM + table epilogue ----------------
__device__ __forceinline__ float ex_relu_tab(float mu, float s, const float2* htab) {
    if (s <= 0.0f) return fmaxf(mu, 0.0f);
    float rs = rsqrtf(s);
    float w  = mu * rs;
    if (w >= 8.0f) return mu;
    if (w <= -8.0f) return 0.0f;
    float ss = s * rs;               // = sqrt(s)
    float p = (w + 8.0f) * 64.0f;
    int i = (int)p;
    float frac = p - (float)i;
    float2 e = htab[i];
    return ss * fmaf(frac, e.y, e.x);
}

// SMEM layout (per buffer), 80-byte row pitch (conflict-free ldmatrix)
#define OFF_A0H 0
#define OFF_AMH 5120
#define OFF_B   10240
#define BUFSZ   38400
#define OFF_HTAB (2 * BUFSZ)              // 76800
#define SM_TOTAL (2 * BUFSZ + 8224)       // 85024

__device__ __forceinline__ void load_chunk(uint32_t sbuf, int nb, int g, int kc) {
    int t = threadIdx.x;
    const char* srcA0 = (const char*)g_S0h;
    const char* srcA2 = (const char*)g_SMh;
#pragma unroll
    for (int j = 0; j < 2; j++) {
        int id = t + j * 256;                 // 512 total
        int tile = id >> 8, rem = id & 255;
        int row = rem >> 2, c16 = rem & 3;
        int node = nb + row; if (node >= NNODES) node = NNODES - 1;
        const char* base = tile == 0 ? srcA0 : srcA2;
        const char* src = base + ((size_t)node * FDIM + kc * 32 + c16 * 8) * 2;
        uint32_t dst = sbuf + OFF_A0H + tile * 5120 + row * 80 + c16 * 16;
        cpasync16(dst, src);
    }
    const char* bp = (const char*)&g_B[g][0];
#pragma unroll
    for (int j = 0; j < 6; j++) {
        int id = t + j * 256;                 // 1408 total
        if (id < 1408) {
            int row = id >> 2, c16 = id & 3;
            const char* src = bp + ((size_t)row * FDIM + kc * 32 + c16 * 8) * 2;
            uint32_t dst = sbuf + OFF_B + row * 80 + c16 * 16;
            cpasync16(dst, src);
        }
    }
}

__global__ __launch_bounds__(256, 2) void gemm_mma_kernel(
    const float* __restrict__ bias, float* __restrict__ out)
{
    extern __shared__ char smem[];
    uint32_t sb = smem_u32(smem);
    int t = threadIdx.x;
    int lane = t & 31, wid = t >> 5;
    int wm = wid & 3, wn = wid >> 2;          // 4 m-tiles x 2 n-tiles
    int nb = blockIdx.y * 64;                 // node tile
    int g  = blockIdx.x;                      // group — A reuse in-wave
    int ob = g * 32;

    // copy h-table into smem (ordered by the first __syncthreads below)
    float2* htab = (float2*)(smem + OFF_HTAB);
    for (int i = t; i < 1025; i += 256) htab[i] = g_htab[i];

    float acc[11][8];
#pragma unroll
    for (int a = 0; a < 11; a++)
#pragma unroll
        for (int d = 0; d < 8; d++) acc[a][d] = 0.0f;

    load_chunk(sb, nb, g, 0);
    CP_COMMIT();

    int arow = wm * 16 + (lane & 15);
    int acolsel = (lane >> 4) << 3;
    int brow = wn * 16 + (lane & 7) + ((lane >> 4) << 3);
    int bcolsel = ((lane >> 3) & 1) << 3;

    for (int c = 0; c < 8; c++) {
        if (c < 7) { load_chunk(sb + ((c + 1) & 1) * BUFSZ, nb, g, c + 1); CP_COMMIT(); CP_WAIT1(); }
        else CP_WAIT0();
        __syncthreads();

        uint32_t b32 = sb + (c & 1) * BUFSZ;
#pragma unroll
        for (int j = 0; j < 2; j++) {
            uint32_t aoff = (uint32_t)(arow * 80 + (j * 16 + acolsel) * 2);
            uint32_t aH[4], aM[4];
            ldsm4(aH, b32 + OFF_A0H + aoff);
            ldsm4(aM, b32 + OFF_AMH + aoff);

            uint32_t boff0 = (uint32_t)(brow * 80 + (j * 16 + bcolsel) * 2);
            uint32_t bq[4];
            // t0 path: S0h * B
            ldsm4(bq, b32 + OFF_B + boff0);
            mma16816(&acc[0][0], aH, &bq[0]); mma16816(&acc[0][4], aH, &bq[2]);
            // SM path: counts * B  (counts exact in fp16)
#pragma unroll
            for (int a = 1; a <= 10; a++) {
                uint32_t boff = boff0 + (uint32_t)(a * 32 * 80);
                ldsm4(bq, b32 + OFF_B + boff);
                mma16816(&acc[a][0], aM, &bq[0]); mma16816(&acc[a][4], aM, &bq[2]);
            }
        }
        __syncthreads();
    }

    int r0 = lane >> 2, c0 = (lane & 3) * 2;
#pragma unroll
    for (int i = 0; i < 2; i++) {
        int node = nb + wm * 16 + r0 + i * 8;
        if (node >= NNODES) continue;
        float deg1 = 1.0f + g_indeg[node];
        float gam[KMIX];
#pragma unroll
        for (int k = 0; k < KMIX; k++) gam[k] = g_gamma[node * KMIX + k];
#pragma unroll
        for (int f = 0; f < 2; f++) {
            int o = ob + wn * 16 + f * 8 + c0;
            float bb0 = bias[o] * deg1;
            float bb1 = bias[o + 1] * deg1;
            int d = f * 4 + i * 2;
            float mu0 = acc[0][d], mu1 = acc[0][d + 1];
            float s0 = 0.f, s1 = 0.f;
#pragma unroll
            for (int k = 0; k < KMIX; k++) {
                s0 += gam[k] * ex_relu_tab(mu0 + acc[1 + 2 * k][d] + bb0,     acc[2 + 2 * k][d],     htab);
                s1 += gam[k] * ex_relu_tab(mu1 + acc[1 + 2 * k][d + 1] + bb1, acc[2 + 2 * k][d + 1], htab);
            }
            *(float2*)&out[(size_t)node * FDIM + o] = make_float2(s0, s1);
        }
    }
}

// ---------------- launcher ----------------
extern "C" void kernel_launch(void* const* d_in, const int* in_sizes, int n_in,
                              void* d_out, int out_size) {
    const float* x       = (const float*)d_in[0];
    const void*  edges   = d_in[1];
    const void*  mask    = d_in[2];
    const float* logp    = (const float*)d_in[3];
    const float* means   = (const float*)d_in[4];
    const float* logvars = (const float*)d_in[5];
    const float* W       = (const float*)d_in[6];
    const float* bias    = (const float*)d_in[7];
    float* out = (float*)d_out;

    int E = in_sizes[1] / 2;

    cudaFuncSetAttribute(gemm_mma_kernel, cudaFuncAttributeMaxDynamicSharedMemorySize, SM_TOTAL);

    init_kernel<<<207, 256>>>(mask, edges, logvars);
    prep_kernel<<<NNODES, 256>>>(mask);

    int eb = (E + 255) / 256;
    count_kernel<<<eb, 256>>>(edges, E);
    scan_kernel<<<1, 1024>>>();
    scatter_kernel<<<eb, 256>>>(edges, E);
    aggregate_kernel<<<NNODES, 256>>>(x, logp, means);

    bprep_kernel<<<8 * 352, 256>>>(W, means, logvars);

    dim3 ggrid(8, (NNODES + 63) / 64);
    gemm_mma_kernel<<<ggrid, 256, SM_TOTAL>>>(bias, out);
}

// round 11
// speedup vs baseline: 1.0556x; 1.0556x over previous
#include <cuda_runtime.h>
#include <cuda_fp16.h>
#include <cstdint>

#define NNODES 50000
#define FDIM   256
#define KMIX   5
#define EMAX   1700000
#define NBLK   196                          // ceil(NNODES/256)

// ---------------- scratch ----------------
__device__ unsigned g_mbits[NNODES * 8];      // bit mask, 256 bits/node
__device__ float g_indeg[NNODES];
__device__ float g_gamma[NNODES * KMIX];
__device__ int   g_flags[2];
__device__ int   g_count[NNODES];
__device__ int   g_cursor[NNODES];
__device__ int   g_locs[NNODES];              // local exclusive scans
__device__ int   g_bsum[NBLK];
__device__ int   g_boff[NBLK + 1];
__device__ int   g_offset[NNODES + 1];
__device__ int   g_sorted[EMAX];
__device__ float g_ivar[KMIX * FDIM];         // exp(-logvars)
__device__ float2 g_htab[1025];               // h(w): value, delta-per-interval
__device__ __half g_S0h[NNODES * FDIM];       // fp16 aggregated S0
__device__ __half g_SMh[NNODES * FDIM];       // aggregated mask counts (exact fp16)
// B concat (single fp16): [group g (32 outs)][352 rows (n)][256 (k)]
__device__ __half g_B[8][352 * 256];

// ---------------- PTX helpers (baseline ISA only) ----------------
__device__ __forceinline__ uint32_t smem_u32(const void* p) {
    uint32_t a;
    asm("{ .reg .u64 t; cvta.to.shared.u64 t, %1; cvt.u32.u64 %0, t; }" : "=r"(a) : "l"(p));
    return a;
}
__device__ __forceinline__ void cpasync16(uint32_t dst, const void* src) {
    asm volatile("cp.async.cg.shared.global [%0], [%1], 16;" :: "r"(dst), "l"(src));
}
#define CP_COMMIT() asm volatile("cp.async.commit_group;" ::: "memory")
#define CP_WAIT1()  asm volatile("cp.async.wait_group 1;" ::: "memory")
#define CP_WAIT0()  asm volatile("cp.async.wait_group 0;" ::: "memory")

__device__ __forceinline__ void ldsm4(uint32_t* r, uint32_t addr) {
    asm volatile("ldmatrix.sync.aligned.m8n8.x4.shared.b16 {%0,%1,%2,%3}, [%4];"
                 : "=r"(r[0]), "=r"(r[1]), "=r"(r[2]), "=r"(r[3]) : "r"(addr));
}
__device__ __forceinline__ void mma16816(float* d, const uint32_t* a, const uint32_t* b) {
    asm volatile("mma.sync.aligned.m16n8k16.row.col.f32.f16.f16.f32 "
                 "{%0,%1,%2,%3}, {%4,%5,%6,%7}, {%8,%9}, {%0,%1,%2,%3};"
                 : "+f"(d[0]), "+f"(d[1]), "+f"(d[2]), "+f"(d[3])
                 : "r"(a[0]), "r"(a[1]), "r"(a[2]), "r"(a[3]), "r"(b[0]), "r"(b[1]));
}

// ---------------- launch 1: zero counters + global dtype detect --------
__global__ void zero_detect_kernel(const void* mask, const void* edges) {
    int b = blockIdx.x, t = threadIdx.x;
    if (b < NBLK) {
        int i = b * 256 + t;
        if (i < NNODES) { g_count[i] = 0; g_cursor[i] = 0; }
    } else {
        int any_m = 0, any_e = 0;
        const unsigned char* mb = (const unsigned char*)mask;
        const int* ei = (const int*)edges;
        for (int i = t; i < 4096; i += 256) {
            if (mb[4 * i + 1] != 0) any_m = 1;
            if (ei[2 * i + 1] != 0) any_e = 1;
        }
        any_m = __syncthreads_or(any_m);
        any_e = __syncthreads_or(any_e);
        if (t == 0) { g_flags[0] = any_m ? 1 : 0; g_flags[1] = any_e ? 0 : 1; }
    }
}

// ---------------- launch 2: megaprep = prep + count + bprep + ivar + htab
__device__ __forceinline__ float h_exact(float w) {
    return 0.3989422804014327f * expf(-0.5f * w * w)
         + 0.5f * w * (1.0f + erff(w * 0.7071067811865476f));
}

__global__ __launch_bounds__(256) void megaprep_kernel(
    const void* __restrict__ mask, const void* __restrict__ edges, int E, int eb,
    const float* __restrict__ W, const float* __restrict__ means,
    const float* __restrict__ logvars)
{
    int b = blockIdx.x, t = threadIdx.x;
    if (b < NNODES) {
        // prep: per-block dtype self-detection (bytes at off%4==1 of this
        // node's bool-range are 0 iff int32 layout; in-bounds either way)
        const unsigned char* mb = (const unsigned char*)mask;
        unsigned char byte = mb[b * 256 + t];
        int isBool = __syncthreads_or(((t & 3) == 1) && byte != 0);
        int m = isBool ? (int)byte : ((const int*)mask)[b * 256 + t];
        unsigned bal = __ballot_sync(0xffffffffu, m);
        if ((t & 31) == 0) g_mbits[b * 8 + (t >> 5)] = bal;
        return;
    }
    b -= NNODES;
    if (b < eb) {
        // count: per-block edge dtype self-detection via src high words
        int i = b * 256 + t;
        int hw = 0;
        if (i < E) hw = ((const int*)edges)[2 * i + 1] != 0;   // in-bounds both layouts
        int isI32 = __syncthreads_or(hw);
        if (i < E) {
            int dst = isI32 ? ((const int*)edges)[E + i]
                            : (int)((const long long*)edges)[E + i];
            atomicAdd(&g_count[dst], 1);
        }
        return;
    }
    b -= eb;
    if (b < 8 * 352) {
        // bprep
        int g = b / 352, n = b % 352;
        float val;
        if (n < 32) {
            val = W[t * FDIM + g * 32 + n];
        } else {
            int mat = (n - 32) >> 5;
            int o = g * 32 + ((n - 32) & 31);
            int k = mat >> 1;
            float w = W[t * FDIM + o];
            if ((mat & 1) == 0) val = means[k * FDIM + t] * w;
            else                val = expf(logvars[k * FDIM + t]) * w * w;
        }
        g_B[g][n * FDIM + t] = __float2half_rn(val);
        return;
    }
    b -= 8 * 352;
    if (b < 5) {
        int i = b * 256 + t;
        if (i < KMIX * FDIM) g_ivar[i] = expf(-logvars[i]);
        return;
    }
    b -= 5;
    {
        int i = b * 256 + t;
        if (i <= 1024) {
            float w0 = -8.0f + i * (1.0f / 64.0f);
            float h0 = h_exact(w0);
            float h1 = h_exact(w0 + (1.0f / 64.0f));
            g_htab[i] = make_float2(h0, h1 - h0);
        }
    }
}

// ---------------- parallel scan (3 small launches) ----------------
__global__ __launch_bounds__(256) void scanA_kernel() {
    int b = blockIdx.x, t = threadIdx.x;
    int i = b * 256 + t;
    int v = (i < NNODES) ? g_count[i] : 0;
    __shared__ int sh[256];
    sh[t] = v;
    __syncthreads();
    for (int off = 1; off < 256; off <<= 1) {
        int u = (t >= off) ? sh[t - off] : 0;
        __syncthreads();
        sh[t] += u;
        __syncthreads();
    }
    if (i < NNODES) g_locs[i] = sh[t] - v;
    if (t == 255) g_bsum[b] = sh[255];
}

__global__ __launch_bounds__(256) void scanB_kernel() {
    int t = threadIdx.x;
    int v = (t < NBLK) ? g_bsum[t] : 0;
    __shared__ int sh[256];
    sh[t] = v;
    __syncthreads();
    for (int off = 1; off < 256; off <<= 1) {
        int u = (t >= off) ? sh[t - off] : 0;
        __syncthreads();
        sh[t] += u;
        __syncthreads();
    }
    if (t < NBLK) g_boff[t] = sh[t] - v;
    if (t == 255) g_boff[NBLK] = sh[255];
}

__global__ __launch_bounds__(256) void scanC_kernel() {
    int b = blockIdx.x, t = threadIdx.x;
    int i = b * 256 + t;
    if (i < NNODES) g_offset[i] = g_locs[i] + g_boff[b];
    if (i == 0) g_offset[NNODES] = g_boff[NBLK];
}

// ---------------- scatter ----------------
__global__ void scatter_kernel(const void* __restrict__ edges, int E) {
    int i = blockIdx.x * blockDim.x + threadIdx.x;
    if (i >= E) return;
    int src, dst;
    if (g_flags[1]) {
        const long long* e = (const long long*)edges;
        src = (int)e[i]; dst = (int)e[E + i];
    } else {
        const int* e = (const int*)edges;
        src = e[i]; dst = e[E + i];
    }
    int pos = atomicAdd(&g_cursor[dst], 1);
    g_sorted[g_offset[dst] + pos] = src;
}

// ---------------- aggregate: CSR gather -> S0h/SMh + indeg + gamma ------
__global__ __launch_bounds__(256) void aggregate_kernel(
    const float* __restrict__ x, const float* __restrict__ logp,
    const float* __restrict__ means)
{
    int n = blockIdx.x;
    int f = threadIdx.x;
    int wsel = f >> 5, bsel = f & 31;
    int wrp = f >> 5, lane = f & 31;

    int beg = g_offset[n], end = g_offset[n + 1];

    unsigned mb = g_mbits[n * 8 + wsel];
    int bit = (mb >> bsel) & 1;
    float xv = __ldg(&x[(size_t)n * FDIM + f]);
    float accS = bit ? 0.0f : xv;
    int cnt = bit;

    // gamma logits partial (self x only)
    float q[KMIX];
#pragma unroll
    for (int k = 0; k < KMIX; k++) {
        float d = xv - __ldg(&means[k * FDIM + f]);
        float iv = g_ivar[k * FDIM + f];
        q[k] = bit ? 0.0f : d * d * iv;
    }

    __shared__ int ssrc[256];
    for (int chunk = beg; chunk < end; chunk += 256) {
        int nload = min(256, end - chunk);
        __syncthreads();
        if (f < nload) ssrc[f] = g_sorted[chunk + f];
        __syncthreads();
        int i = 0;
        for (; i + 4 <= nload; i += 4) {
            int s0 = ssrc[i], s1 = ssrc[i + 1], s2 = ssrc[i + 2], s3 = ssrc[i + 3];
            unsigned m0 = __ldg(&g_mbits[s0 * 8 + wsel]);
            unsigned m1 = __ldg(&g_mbits[s1 * 8 + wsel]);
            unsigned m2 = __ldg(&g_mbits[s2 * 8 + wsel]);
            unsigned m3 = __ldg(&g_mbits[s3 * 8 + wsel]);
            float v0 = __ldg(&x[(size_t)s0 * FDIM + f]);
            float v1 = __ldg(&x[(size_t)s1 * FDIM + f]);
            float v2 = __ldg(&x[(size_t)s2 * FDIM + f]);
            float v3 = __ldg(&x[(size_t)s3 * FDIM + f]);
            int b0 = (m0 >> bsel) & 1, b1 = (m1 >> bsel) & 1;
            int b2 = (m2 >> bsel) & 1, b3 = (m3 >> bsel) & 1;
            accS += b0 ? 0.0f : v0;
            accS += b1 ? 0.0f : v1;
            accS += b2 ? 0.0f : v2;
            accS += b3 ? 0.0f : v3;
            cnt += b0 + b1 + b2 + b3;
        }
        for (; i < nload; i++) {
            int s0 = ssrc[i];
            unsigned m0 = __ldg(&g_mbits[s0 * 8 + wsel]);
            float v0 = __ldg(&x[(size_t)s0 * FDIM + f]);
            int b0 = (m0 >> bsel) & 1;
            accS += b0 ? 0.0f : v0;
            cnt += b0;
        }
    }

    int idx = n * FDIM + f;
    g_S0h[idx] = __float2half_rn(accS);
    g_SMh[idx] = __float2half_rn((float)cnt);
    if (f == 0) g_indeg[n] = (float)(end - beg);

    // gamma reduction + softmax
#pragma unroll
    for (int k = 0; k < KMIX; k++)
        for (int off = 16; off; off >>= 1)
            q[k] += __shfl_down_sync(0xffffffffu, q[k], off);
    __shared__ float red[8][KMIX];
    if (lane == 0)
#pragma unroll
        for (int k = 0; k < KMIX; k++) red[wrp][k] = q[k];
    __syncthreads();
    if (f == 0) {
        float l[KMIX], mx = -1e30f;
#pragma unroll
        for (int k = 0; k < KMIX; k++) {
            float s = 0.f;
            for (int ww = 0; ww < 8; ww++) s += red[ww][k];
            l[k] = logp[k] - 0.5f * s;
            mx = fmaxf(mx, l[k]);
        }
        float e[KMIX], se = 0.f;
#pragma unroll
        for (int k = 0; k < KMIX; k++) { e[k] = __expf(l[k] - mx); se += e[k]; }
        float inv = 1.0f / se;
#pragma unroll
        for (int k = 0; k < KMIX; k++) g_gamma[n * KMIX + k] = e[k] * inv;
    }
}

// ---------------- mma.sync GEMM + table epilogue ----------------
__device__ __forceinline__ float ex_relu_tab(float mu, float s, const float2* htab) {
    if (s <= 0.0f) return fmaxf(mu, 0.0f);
    float rs = rsqrtf(s);
    float w  = mu * rs;
    if (w >= 8.0f) return mu;
    if (w <= -8.0f) return 0.0f;
    float ss = s * rs;               // = sqrt(s)
    float p = (w + 8.0f) * 64.0f;
    int i = (int)p;
    float frac = p - (float)i;
    float2 e = htab[i];
    return ss * fmaf(frac, e.y, e.x);
}

// SMEM layout (per buffer), 80-byte row pitch (conflict-free ldmatrix)
#define OFF_A0H 0
#define OFF_AMH 5120
#define OFF_B   10240
#define BUFSZ   38400
#define OFF_HTAB (2 * BUFSZ)              // 76800
#define SM_TOTAL (2 * BUFSZ + 8224)       // 85024

__device__ __forceinline__ void load_chunk(uint32_t sbuf, int nb, int g, int kc) {
    int t = threadIdx.x;
    const char* srcA0 = (const char*)g_S0h;
    const char* srcA2 = (const char*)g_SMh;
#pragma unroll
    for (int j = 0; j < 2; j++) {
        int id = t + j * 256;                 // 512 total
        int tile = id >> 8, rem = id & 255;
        int row = rem >> 2, c16 = rem & 3;
        int node = nb + row; if (node >= NNODES) node = NNODES - 1;
        const char* base = tile == 0 ? srcA0 : srcA2;
        const char* src = base + ((size_t)node * FDIM + kc * 32 + c16 * 8) * 2;
        uint32_t dst = sbuf + OFF_A0H + tile * 5120 + row * 80 + c16 * 16;
        cpasync16(dst, src);
    }
    const char* bp = (const char*)&g_B[g][0];
#pragma unroll
    for (int j = 0; j < 6; j++) {
        int id = t + j * 256;                 // 1408 total
        if (id < 1408) {
            int row = id >> 2, c16 = id & 3;
            const char* src = bp + ((size_t)row * FDIM + kc * 32 + c16 * 8) * 2;
            uint32_t dst = sbuf + OFF_B + row * 80 + c16 * 16;
            cpasync16(dst, src);
        }
    }
}

__global__ __launch_bounds__(256, 2) void gemm_mma_kernel(
    const float* __restrict__ bias, float* __restrict__ out)
{
    extern __shared__ char smem[];
    uint32_t sb = smem_u32(smem);
    int t = threadIdx.x;
    int lane = t & 31, wid = t >> 5;
    int wm = wid & 3, wn = wid >> 2;          // 4 m-tiles x 2 n-tiles
    int nb = blockIdx.y * 64;                 // node tile
    int g  = blockIdx.x;                      // group — A reuse in-wave
    int ob = g * 32;

    // copy h-table into smem (ordered by the first __syncthreads below)
    float2* htab = (float2*)(smem + OFF_HTAB);
    for (int i = t; i < 1025; i += 256) htab[i] = g_htab[i];

    float acc[11][8];
#pragma unroll
    for (int a = 0; a < 11; a++)
#pragma unroll
        for (int d = 0; d < 8; d++) acc[a][d] = 0.0f;

    load_chunk(sb, nb, g, 0);
    CP_COMMIT();

    int arow = wm * 16 + (lane & 15);
    int acolsel = (lane >> 4) << 3;
    int brow = wn * 16 + (lane & 7) + ((lane >> 4) << 3);
    int bcolsel = ((lane >> 3) & 1) << 3;

    for (int c = 0; c < 8; c++) {
        if (c < 7) { load_chunk(sb + ((c + 1) & 1) * BUFSZ, nb, g, c + 1); CP_COMMIT(); CP_WAIT1(); }
        else CP_WAIT0();
        __syncthreads();

        uint32_t b32 = sb + (c & 1) * BUFSZ;
#pragma unroll
        for (int j = 0; j < 2; j++) {
            uint32_t aoff = (uint32_t)(arow * 80 + (j * 16 + acolsel) * 2);
            uint32_t aH[4], aM[4];
            ldsm4(aH, b32 + OFF_A0H + aoff);
            ldsm4(aM, b32 + OFF_AMH + aoff);

            uint32_t boff0 = (uint32_t)(brow * 80 + (j * 16 + bcolsel) * 2);
            uint32_t bq[4];
            // t0 path: S0h * B
            ldsm4(bq, b32 + OFF_B + boff0);
            mma16816(&acc[0][0], aH, &bq[0]); mma16816(&acc[0][4], aH, &bq[2]);
            // SM path: counts * B  (counts exact in fp16)
#pragma unroll
            for (int a = 1; a <= 10; a++) {
                uint32_t boff = boff0 + (uint32_t)(a * 32 * 80);
                ldsm4(bq, b32 + OFF_B + boff);
                mma16816(&acc[a][0], aM, &bq[0]); mma16816(&acc[a][4], aM, &bq[2]);
            }
        }
        __syncthreads();
    }

    int r0 = lane >> 2, c0 = (lane & 3) * 2;
#pragma unroll
    for (int i = 0; i < 2; i++) {
        int node = nb + wm * 16 + r0 + i * 8;
        if (node >= NNODES) continue;
        float deg1 = 1.0f + g_indeg[node];
        float gam[KMIX];
#pragma unroll
        for (int k = 0; k < KMIX; k++) gam[k] = g_gamma[node * KMIX + k];
#pragma unroll
        for (int f = 0; f < 2; f++) {
            int o = ob + wn * 16 + f * 8 + c0;
            float bb0 = bias[o] * deg1;
            float bb1 = bias[o + 1] * deg1;
            int d = f * 4 + i * 2;
            float mu0 = acc[0][d], mu1 = acc[0][d + 1];
            float s0 = 0.f, s1 = 0.f;
#pragma unroll
            for (int k = 0; k < KMIX; k++) {
                s0 += gam[k] * ex_relu_tab(mu0 + acc[1 + 2 * k][d] + bb0,     acc[2 + 2 * k][d],     htab);
                s1 += gam[k] * ex_relu_tab(mu1 + acc[1 + 2 * k][d + 1] + bb1, acc[2 + 2 * k][d + 1], htab);
            }
            *(float2*)&out[(size_t)node * FDIM + o] = make_float2(s0, s1);
        }
    }
}

// ---------------- launcher ----------------
extern "C" void kernel_launch(void* const* d_in, const int* in_sizes, int n_in,
                              void* d_out, int out_size) {
    const float* x       = (const float*)d_in[0];
    const void*  edges   = d_in[1];
    const void*  mask    = d_in[2];
    const float* logp    = (const float*)d_in[3];
    const float* means   = (const float*)d_in[4];
    const float* logvars = (const float*)d_in[5];
    const float* W       = (const float*)d_in[6];
    const float* bias    = (const float*)d_in[7];
    float* out = (float*)d_out;

    int E = in_sizes[1] / 2;
    int eb = (E + 255) / 256;

    cudaFuncSetAttribute(gemm_mma_kernel, cudaFuncAttributeMaxDynamicSharedMemorySize, SM_TOTAL);

    zero_detect_kernel<<<NBLK + 1, 256>>>(mask, edges);
    megaprep_kernel<<<NNODES + eb + 8 * 352 + 10, 256>>>(mask, edges, E, eb, W, means, logvars);
    scanA_kernel<<<NBLK, 256>>>();
    scanB_kernel<<<1, 256>>>();
    scanC_kernel<<<NBLK, 256>>>();
    scatter_kernel<<<eb, 256>>>(edges, E);
    aggregate_kernel<<<NNODES, 256>>>(x, logp, means);

    dim3 ggrid(8, (NNODES + 63) / 64);
    gemm_mma_kernel<<<ggrid, 256, SM_TOTAL>>>(bias, out);
}

// round 12
// speedup vs baseline: 1.1482x; 1.0877x over previous
#include <cuda_runtime.h>
#include <cuda_fp16.h>
#include <cstdint>

#define NNODES 50000
#define FDIM   256
#define KMIX   5
#define EMAX   1700000
#define NBLK   196                          // ceil(NNODES/256)

// ---------------- scratch ----------------
__device__ unsigned g_mbits[NNODES * 8];      // bit mask, 256 bits/node
__device__ float g_indeg[NNODES];
__device__ float g_gamma[NNODES * KMIX];
__device__ int   g_flags[2];
__device__ int   g_count[NNODES];
__device__ int   g_cursor[NNODES];
__device__ int   g_locs[NNODES];              // local exclusive scans
__device__ int   g_bsum[NBLK];
__device__ int   g_boff[NBLK + 1];
__device__ int   g_sorted[EMAX];
__device__ float g_ivar[KMIX * FDIM];         // exp(-logvars)
__device__ float2 g_htab[1025];               // h(w): value, delta-per-interval
__device__ __half g_x0h[NNODES * FDIM];       // fp16 masked x (gather source)
__device__ __half g_S0h[NNODES * FDIM];       // fp16 aggregated S0
__device__ __half g_SMh[NNODES * FDIM];       // aggregated mask counts (exact fp16)
// B concat (single fp16): [group g (32 outs)][352 rows (n)][256 (k)]
__device__ __half g_B[8][352 * 256];

// ---------------- PTX helpers (baseline ISA only) ----------------
__device__ __forceinline__ uint32_t smem_u32(const void* p) {
    uint32_t a;
    asm("{ .reg .u64 t; cvta.to.shared.u64 t, %1; cvt.u32.u64 %0, t; }" : "=r"(a) : "l"(p));
    return a;
}
__device__ __forceinline__ void cpasync16(uint32_t dst, const void* src) {
    asm volatile("cp.async.cg.shared.global [%0], [%1], 16;" :: "r"(dst), "l"(src));
}
#define CP_COMMIT() asm volatile("cp.async.commit_group;" ::: "memory")
#define CP_WAIT1()  asm volatile("cp.async.wait_group 1;" ::: "memory")
#define CP_WAIT0()  asm volatile("cp.async.wait_group 0;" ::: "memory")

__device__ __forceinline__ void ldsm4(uint32_t* r, uint32_t addr) {
    asm volatile("ldmatrix.sync.aligned.m8n8.x4.shared.b16 {%0,%1,%2,%3}, [%4];"
                 : "=r"(r[0]), "=r"(r[1]), "=r"(r[2]), "=r"(r[3]) : "r"(addr));
}
__device__ __forceinline__ void mma16816(float* d, const uint32_t* a, const uint32_t* b) {
    asm volatile("mma.sync.aligned.m16n8k16.row.col.f32.f16.f16.f32 "
                 "{%0,%1,%2,%3}, {%4,%5,%6,%7}, {%8,%9}, {%0,%1,%2,%3};"
                 : "+f"(d[0]), "+f"(d[1]), "+f"(d[2]), "+f"(d[3])
                 : "r"(a[0]), "r"(a[1]), "r"(a[2]), "r"(a[3]), "r"(b[0]), "r"(b[1]));
}

// ---------------- launch 1: zero counters + global dtype detect --------
__global__ void zero_detect_kernel(const void* mask, const void* edges) {
    int b = blockIdx.x, t = threadIdx.x;
    if (b < NBLK) {
        int i = b * 256 + t;
        if (i < NNODES) { g_count[i] = 0; g_cursor[i] = 0; }
    } else {
        int any_m = 0, any_e = 0;
        const unsigned char* mb = (const unsigned char*)mask;
        const int* ei = (const int*)edges;
        for (int i = t; i < 4096; i += 256) {
            if (mb[4 * i + 1] != 0) any_m = 1;
            if (ei[2 * i + 1] != 0) any_e = 1;
        }
        any_m = __syncthreads_or(any_m);
        any_e = __syncthreads_or(any_e);
        if (t == 0) { g_flags[0] = any_m ? 1 : 0; g_flags[1] = any_e ? 0 : 1; }
    }
}

// ---------------- launch 2: megaprep = prep+x0h + count + bprep + ivar + htab
__device__ __forceinline__ float h_exact(float w) {
    return 0.3989422804014327f * expf(-0.5f * w * w)
         + 0.5f * w * (1.0f + erff(w * 0.7071067811865476f));
}

__global__ __launch_bounds__(256) void megaprep_kernel(
    const void* __restrict__ mask, const void* __restrict__ edges, int E, int eb,
    const float* __restrict__ x,
    const float* __restrict__ W, const float* __restrict__ means,
    const float* __restrict__ logvars)
{
    int b = blockIdx.x, t = threadIdx.x;
    if (b < NNODES) {
        // prep: per-block dtype self-detection (bytes at off%4==1 of this
        // node's bool-range are 0 iff int32 layout; in-bounds either way)
        const unsigned char* mb = (const unsigned char*)mask;
        unsigned char byte = mb[b * 256 + t];
        int isBool = __syncthreads_or(((t & 3) == 1) && byte != 0);
        int m = isBool ? (int)byte : ((const int*)mask)[b * 256 + t];
        unsigned bal = __ballot_sync(0xffffffffu, m);
        if ((t & 31) == 0) g_mbits[b * 8 + (t >> 5)] = bal;
        float xv = x[b * 256 + t];
        g_x0h[b * 256 + t] = __float2half_rn(m ? 0.0f : xv);
        return;
    }
    b -= NNODES;
    if (b < eb) {
        // count: per-block edge dtype self-detection via src high words
        int i = b * 256 + t;
        int hw = 0;
        if (i < E) hw = ((const int*)edges)[2 * i + 1] != 0;   // in-bounds both layouts
        int isI32 = __syncthreads_or(hw);
        if (i < E) {
            int dst = isI32 ? ((const int*)edges)[E + i]
                            : (int)((const long long*)edges)[E + i];
            atomicAdd(&g_count[dst], 1);
        }
        return;
    }
    b -= eb;
    if (b < 8 * 352) {
        // bprep
        int g = b / 352, n = b % 352;
        float val;
        if (n < 32) {
            val = W[t * FDIM + g * 32 + n];
        } else {
            int mat = (n - 32) >> 5;
            int o = g * 32 + ((n - 32) & 31);
            int k = mat >> 1;
            float w = W[t * FDIM + o];
            if ((mat & 1) == 0) val = means[k * FDIM + t] * w;
            else                val = expf(logvars[k * FDIM + t]) * w * w;
        }
        g_B[g][n * FDIM + t] = __float2half_rn(val);
        return;
    }
    b -= 8 * 352;
    if (b < 5) {
        int i = b * 256 + t;
        if (i < KMIX * FDIM) g_ivar[i] = expf(-logvars[i]);
        return;
    }
    b -= 5;
    {
        int i = b * 256 + t;
        if (i <= 1024) {
            float w0 = -8.0f + i * (1.0f / 64.0f);
            float h0 = h_exact(w0);
            float h1 = h_exact(w0 + (1.0f / 64.0f));
            g_htab[i] = make_float2(h0, h1 - h0);
        }
    }
}

// ---------------- parallel scan (2 small launches; offsets inline later)
__global__ __launch_bounds__(256) void scanA_kernel() {
    int b = blockIdx.x, t = threadIdx.x;
    int i = b * 256 + t;
    int v = (i < NNODES) ? g_count[i] : 0;
    __shared__ int sh[256];
    sh[t] = v;
    __syncthreads();
    for (int off = 1; off < 256; off <<= 1) {
        int u = (t >= off) ? sh[t - off] : 0;
        __syncthreads();
        sh[t] += u;
        __syncthreads();
    }
    if (i < NNODES) g_locs[i] = sh[t] - v;
    if (t == 255) g_bsum[b] = sh[255];
}

__global__ __launch_bounds__(256) void scanB_kernel() {
    int t = threadIdx.x;
    int v = (t < NBLK) ? g_bsum[t] : 0;
    __shared__ int sh[256];
    sh[t] = v;
    __syncthreads();
    for (int off = 1; off < 256; off <<= 1) {
        int u = (t >= off) ? sh[t - off] : 0;
        __syncthreads();
        sh[t] += u;
        __syncthreads();
    }
    if (t < NBLK) g_boff[t] = sh[t] - v;
    if (t == 255) g_boff[NBLK] = sh[255];
}

__device__ __forceinline__ int node_offset(int n) {
    return (n < NNODES) ? (g_locs[n] + g_boff[n >> 8]) : g_boff[NBLK];
}

// ---------------- scatter (offsets computed inline) ----------------
__global__ void scatter_kernel(const void* __restrict__ edges, int E) {
    int i = blockIdx.x * blockDim.x + threadIdx.x;
    if (i >= E) return;
    int src, dst;
    if (g_flags[1]) {
        const long long* e = (const long long*)edges;
        src = (int)e[i]; dst = (int)e[E + i];
    } else {
        const int* e = (const int*)edges;
        src = e[i]; dst = e[E + i];
    }
    int pos = atomicAdd(&g_cursor[dst], 1);
    g_sorted[g_locs[dst] + g_boff[dst >> 8] + pos] = src;
}

// ---------------- aggregate: fp16 CSR gather -> S0h/SMh + indeg + gamma --
__global__ __launch_bounds__(256) void aggregate_kernel(
    const float* __restrict__ x, const float* __restrict__ logp,
    const float* __restrict__ means)
{
    int n = blockIdx.x;
    int f = threadIdx.x;
    int wsel = f >> 5, bsel = f & 31;
    int wrp = f >> 5, lane = f & 31;

    int beg = node_offset(n), end = node_offset(n + 1);

    unsigned mb = g_mbits[n * 8 + wsel];
    int bit = (mb >> bsel) & 1;
    float xv = __ldg(&x[(size_t)n * FDIM + f]);
    float accS = bit ? 0.0f : xv;
    int cnt = bit;

    // gamma logits partial (self x only)
    float q[KMIX];
#pragma unroll
    for (int k = 0; k < KMIX; k++) {
        float d = xv - __ldg(&means[k * FDIM + f]);
        float iv = g_ivar[k * FDIM + f];
        q[k] = bit ? 0.0f : d * d * iv;
    }

    __shared__ int ssrc[256];
    for (int chunk = beg; chunk < end; chunk += 256) {
        int nload = min(256, end - chunk);
        __syncthreads();
        if (f < nload) ssrc[f] = g_sorted[chunk + f];
        __syncthreads();
        int i = 0;
        for (; i + 4 <= nload; i += 4) {
            int s0 = ssrc[i], s1 = ssrc[i + 1], s2 = ssrc[i + 2], s3 = ssrc[i + 3];
            unsigned m0 = __ldg(&g_mbits[s0 * 8 + wsel]);
            unsigned m1 = __ldg(&g_mbits[s1 * 8 + wsel]);
            unsigned m2 = __ldg(&g_mbits[s2 * 8 + wsel]);
            unsigned m3 = __ldg(&g_mbits[s3 * 8 + wsel]);
            float v0 = __half2float(__ldg(&g_x0h[(size_t)s0 * FDIM + f]));
            float v1 = __half2float(__ldg(&g_x0h[(size_t)s1 * FDIM + f]));
            float v2 = __half2float(__ldg(&g_x0h[(size_t)s2 * FDIM + f]));
            float v3 = __half2float(__ldg(&g_x0h[(size_t)s3 * FDIM + f]));
            accS += (v0 + v1) + (v2 + v3);      // mask pre-applied in x0h
            cnt += ((m0 >> bsel) & 1) + ((m1 >> bsel) & 1)
                 + ((m2 >> bsel) & 1) + ((m3 >> bsel) & 1);
        }
        for (; i < nload; i++) {
            int s0 = ssrc[i];
            unsigned m0 = __ldg(&g_mbits[s0 * 8 + wsel]);
            accS += __half2float(__ldg(&g_x0h[(size_t)s0 * FDIM + f]));
            cnt += (m0 >> bsel) & 1;
        }
    }

    int idx = n * FDIM + f;
    g_S0h[idx] = __float2half_rn(accS);
    g_SMh[idx] = __float2half_rn((float)cnt);
    if (f == 0) g_indeg[n] = (float)(end - beg);

    // gamma reduction + softmax
#pragma unroll
    for (int k = 0; k < KMIX; k++)
        for (int off = 16; off; off >>= 1)
            q[k] += __shfl_down_sync(0xffffffffu, q[k], off);
    __shared__ float red[8][KMIX];
    if (lane == 0)
#pragma unroll
        for (int k = 0; k < KMIX; k++) red[wrp][k] = q[k];
    __syncthreads();
    if (f == 0) {
        float l[KMIX], mx = -1e30f;
#pragma unroll
        for (int k = 0; k < KMIX; k++) {
            float s = 0.f;
            for (int ww = 0; ww < 8; ww++) s += red[ww][k];
            l[k] = logp[k] - 0.5f * s;
            mx = fmaxf(mx, l[k]);
        }
        float e[KMIX], se = 0.f;
#pragma unroll
        for (int k = 0; k < KMIX; k++) { e[k] = __expf(l[k] - mx); se += e[k]; }
        float inv = 1.0f / se;
#pragma unroll
        for (int k = 0; k < KMIX; k++) g_gamma[n * KMIX + k] = e[k] * inv;
    }
}

// ---------------- mma.sync GEMM + table epilogue ----------------
__device__ __forceinline__ float ex_relu_tab(float mu, float s, const float2* htab) {
    if (s <= 0.0f) return fmaxf(mu, 0.0f);
    float rs = rsqrtf(s);
    float w  = mu * rs;
    if (w >= 8.0f) return mu;
    if (w <= -8.0f) return 0.0f;
    float ss = s * rs;               // = sqrt(s)
    float p = (w + 8.0f) * 64.0f;
    int i = (int)p;
    float frac = p - (float)i;
    float2 e = htab[i];
    return ss * fmaf(frac, e.y, e.x);
}

// SMEM layout (per buffer), 80-byte row pitch (conflict-free ldmatrix)
#define OFF_A0H 0
#define OFF_AMH 5120
#define OFF_B   10240
#define BUFSZ   38400
#define OFF_HTAB (2 * BUFSZ)              // 76800
#define SM_TOTAL (2 * BUFSZ + 8224)       // 85024

__device__ __forceinline__ void load_chunk(uint32_t sbuf, int nb, int g, int kc) {
    int t = threadIdx.x;
    const char* srcA0 = (const char*)g_S0h;
    const char* srcA2 = (const char*)g_SMh;
#pragma unroll
    for (int j = 0; j < 2; j++) {
        int id = t + j * 256;                 // 512 total
        int tile = id >> 8, rem = id & 255;
        int row = rem >> 2, c16 = rem & 3;
        int node = nb + row; if (node >= NNODES) node = NNODES - 1;
        const char* base = tile == 0 ? srcA0 : srcA2;
        const char* src = base + ((size_t)node * FDIM + kc * 32 + c16 * 8) * 2;
        uint32_t dst = sbuf + OFF_A0H + tile * 5120 + row * 80 + c16 * 16;
        cpasync16(dst, src);
    }
    const char* bp = (const char*)&g_B[g][0];
#pragma unroll
    for (int j = 0; j < 6; j++) {
        int id = t + j * 256;                 // 1408 total
        if (id < 1408) {
            int row = id >> 2, c16 = id & 3;
            const char* src = bp + ((size_t)row * FDIM + kc * 32 + c16 * 8) * 2;
            uint32_t dst = sbuf + OFF_B + row * 80 + c16 * 16;
            cpasync16(dst, src);
        }
    }
}

__global__ __launch_bounds__(256, 2) void gemm_mma_kernel(
    const float* __restrict__ bias, float* __restrict__ out)
{
    extern __shared__ char smem[];
    uint32_t sb = smem_u32(smem);
    int t = threadIdx.x;
    int lane = t & 31, wid = t >> 5;
    int wm = wid & 3, wn = wid >> 2;          // 4 m-tiles x 2 n-tiles
    int nb = blockIdx.y * 64;                 // node tile
    int g  = blockIdx.x;                      // group — A reuse in-wave
    int ob = g * 32;

    // copy h-table into smem (ordered by the first __syncthreads below)
    float2* htab = (float2*)(smem + OFF_HTAB);
    for (int i = t; i < 1025; i += 256) htab[i] = g_htab[i];

    float acc[11][8];
#pragma unroll
    for (int a = 0; a < 11; a++)
#pragma unroll
        for (int d = 0; d < 8; d++) acc[a][d] = 0.0f;

    load_chunk(sb, nb, g, 0);
    CP_COMMIT();

    int arow = wm * 16 + (lane & 15);
    int acolsel = (lane >> 4) << 3;
    int brow = wn * 16 + (lane & 7) + ((lane >> 4) << 3);
    int bcolsel = ((lane >> 3) & 1) << 3;

    for (int c = 0; c < 8; c++) {
        if (c < 7) { load_chunk(sb + ((c + 1) & 1) * BUFSZ, nb, g, c + 1); CP_COMMIT(); CP_WAIT1(); }
        else CP_WAIT0();
        __syncthreads();

        uint32_t b32 = sb + (c & 1) * BUFSZ;
#pragma unroll
        for (int j = 0; j < 2; j++) {
            uint32_t aoff = (uint32_t)(arow * 80 + (j * 16 + acolsel) * 2);
            uint32_t aH[4], aM[4];
            ldsm4(aH, b32 + OFF_A0H + aoff);
            ldsm4(aM, b32 + OFF_AMH + aoff);

            uint32_t boff0 = (uint32_t)(brow * 80 + (j * 16 + bcolsel) * 2);
            uint32_t bq[4];
            // t0 path: S0h * B
            ldsm4(bq, b32 + OFF_B + boff0);
            mma16816(&acc[0][0], aH, &bq[0]); mma16816(&acc[0][4], aH, &bq[2]);
            // SM path: counts * B  (counts exact in fp16)
#pragma unroll
            for (int a = 1; a <= 10; a++) {
                uint32_t boff = boff0 + (uint32_t)(a * 32 * 80);
                ldsm4(bq, b32 + OFF_B + boff);
                mma16816(&acc[a][0], aM, &bq[0]); mma16816(&acc[a][4], aM, &bq[2]);
            }
        }
        __syncthreads();
    }

    int r0 = lane >> 2, c0 = (lane & 3) * 2;
#pragma unroll
    for (int i = 0; i < 2; i++) {
        int node = nb + wm * 16 + r0 + i * 8;
        if (node >= NNODES) continue;
        float deg1 = 1.0f + g_indeg[node];
        float gam[KMIX];
#pragma unroll
        for (int k = 0; k < KMIX; k++) gam[k] = g_gamma[node * KMIX + k];
#pragma unroll
        for (int f = 0; f < 2; f++) {
            int o = ob + wn * 16 + f * 8 + c0;
            float bb0 = bias[o] * deg1;
            float bb1 = bias[o + 1] * deg1;
            int d = f * 4 + i * 2;
            float mu0 = acc[0][d], mu1 = acc[0][d + 1];
            float s0 = 0.f, s1 = 0.f;
#pragma unroll
            for (int k = 0; k < KMIX; k++) {
                s0 += gam[k] * ex_relu_tab(mu0 + acc[1 + 2 * k][d] + bb0,     acc[2 + 2 * k][d],     htab);
                s1 += gam[k] * ex_relu_tab(mu1 + acc[1 + 2 * k][d + 1] + bb1, acc[2 + 2 * k][d + 1], htab);
            }
            *(float2*)&out[(size_t)node * FDIM + o] = make_float2(s0, s1);
        }
    }
}

// ---------------- launcher ----------------
extern "C" void kernel_launch(void* const* d_in, const int* in_sizes, int n_in,
                              void* d_out, int out_size) {
    const float* x       = (const float*)d_in[0];
    const void*  edges   = d_in[1];
    const void*  mask    = d_in[2];
    const float* logp    = (const float*)d_in[3];
    const float* means   = (const float*)d_in[4];
    const float* logvars = (const float*)d_in[5];
    const float* W       = (const float*)d_in[6];
    const float* bias    = (const float*)d_in[7];
    float* out = (float*)d_out;

    int E = in_sizes[1] / 2;
    int eb = (E + 255) / 256;

    cudaFuncSetAttribute(gemm_mma_kernel, cudaFuncAttributeMaxDynamicSharedMemorySize, SM_TOTAL);

    zero_detect_kernel<<<NBLK + 1, 256>>>(mask, edges);
    megaprep_kernel<<<NNODES + eb + 8 * 352 + 10, 256>>>(mask, edges, E, eb, x, W, means, logvars);
    scanA_kernel<<<NBLK, 256>>>();
    scanB_kernel<<<1, 256>>>();
    scatter_kernel<<<eb, 256>>>(edges, E);
    aggregate_kernel<<<NNODES, 256>>>(x, logp, means);

    dim3 ggrid(8, (NNODES + 63) / 64);
    gemm_mma_kernel<<<ggrid, 256, SM_TOTAL>>>(bias, out);
}

// round 13
// speedup vs baseline: 1.5289x; 1.3316x over previous
#include <cuda_runtime.h>
#include <cuda_fp16.h>
#include <cstdint>

#define NNODES 50000
#define FDIM   256
#define KMIX   5
#define EMAX   1700000
#define NBLK   196                          // ceil(NNODES/256)
#define PBLK   (NNODES / 4)                 // 12500 prep blocks (4 nodes each)

// ---------------- scratch ----------------
__device__ unsigned g_mbits[NNODES * 8];      // bit mask, 256 bits/node
__device__ float g_indeg[NNODES];
__device__ float g_gamma[NNODES * KMIX];
__device__ int   g_flags[2];
__device__ int   g_count[NNODES];
__device__ int   g_cursor[NNODES];
__device__ int   g_locs[NNODES];              // local exclusive scans
__device__ int   g_bsum[NBLK];
__device__ int   g_boff[NBLK + 1];
__device__ int   g_sorted[EMAX];
__device__ float g_ivar[KMIX * FDIM];         // exp(-logvars)
__device__ float2 g_htab[1025];               // h(w): value, delta-per-interval
__device__ __half g_x0h[NNODES * FDIM];       // fp16 masked x (gather source)
__device__ __half g_S0h[NNODES * FDIM];       // fp16 aggregated S0
__device__ __half g_SMh[NNODES * FDIM];       // aggregated mask counts (exact fp16)
// B concat (single fp16): [group g (32 outs)][352 rows (n)][256 (k)]
__device__ __half g_B[8][352 * 256];

// ---------------- PTX helpers (baseline ISA only) ----------------
__device__ __forceinline__ uint32_t smem_u32(const void* p) {
    uint32_t a;
    asm("{ .reg .u64 t; cvta.to.shared.u64 t, %1; cvt.u32.u64 %0, t; }" : "=r"(a) : "l"(p));
    return a;
}
__device__ __forceinline__ void cpasync16(uint32_t dst, const void* src) {
    asm volatile("cp.async.cg.shared.global [%0], [%1], 16;" :: "r"(dst), "l"(src));
}
#define CP_COMMIT() asm volatile("cp.async.commit_group;" ::: "memory")
#define CP_WAIT1()  asm volatile("cp.async.wait_group 1;" ::: "memory")
#define CP_WAIT0()  asm volatile("cp.async.wait_group 0;" ::: "memory")

__device__ __forceinline__ void ldsm4(uint32_t* r, uint32_t addr) {
    asm volatile("ldmatrix.sync.aligned.m8n8.x4.shared.b16 {%0,%1,%2,%3}, [%4];"
                 : "=r"(r[0]), "=r"(r[1]), "=r"(r[2]), "=r"(r[3]) : "r"(addr));
}
__device__ __forceinline__ void mma16816(float* d, const uint32_t* a, const uint32_t* b) {
    asm volatile("mma.sync.aligned.m16n8k16.row.col.f32.f16.f16.f32 "
                 "{%0,%1,%2,%3}, {%4,%5,%6,%7}, {%8,%9}, {%0,%1,%2,%3};"
                 : "+f"(d[0]), "+f"(d[1]), "+f"(d[2]), "+f"(d[3])
                 : "r"(a[0]), "r"(a[1]), "r"(a[2]), "r"(a[3]), "r"(b[0]), "r"(b[1]));
}

// ---------------- launch 1: zero counters + global dtype detect --------
__global__ void zero_detect_kernel(const void* mask, const void* edges) {
    int b = blockIdx.x, t = threadIdx.x;
    if (b < NBLK) {
        int i = b * 256 + t;
        if (i < NNODES) { g_count[i] = 0; g_cursor[i] = 0; }
    } else {
        int any_m = 0, any_e = 0;
        const unsigned char* mb = (const unsigned char*)mask;
        const int* ei = (const int*)edges;
        for (int i = t; i < 4096; i += 256) {
            if (mb[4 * i + 1] != 0) any_m = 1;
            if (ei[2 * i + 1] != 0) any_e = 1;
        }
        any_m = __syncthreads_or(any_m);
        any_e = __syncthreads_or(any_e);
        if (t == 0) { g_flags[0] = any_m ? 1 : 0; g_flags[1] = any_e ? 0 : 1; }
    }
}

// ---------------- launch 2: megaprep = prep+x0h + count + bprep + ivar + htab
__device__ __forceinline__ float h_exact(float w) {
    return 0.3989422804014327f * expf(-0.5f * w * w)
         + 0.5f * w * (1.0f + erff(w * 0.7071067811865476f));
}

__global__ __launch_bounds__(256) void megaprep_kernel(
    const void* __restrict__ mask, const void* __restrict__ edges, int E, int eb,
    const float* __restrict__ x,
    const float* __restrict__ W, const float* __restrict__ means,
    const float* __restrict__ logvars)
{
    int b = blockIdx.x, t = threadIdx.x;
    if (b < PBLK) {
        // prep: 4 nodes/block, 64 threads/node, 4 features/thread
        int node = b * 4 + (t >> 6);
        int u = t & 63;
        int m0, m1, m2, m3;
        if (g_flags[0]) {
            uchar4 w = ((const uchar4*)mask)[node * 64 + u];
            m0 = w.x; m1 = w.y; m2 = w.z; m3 = w.w;
        } else {
            int4 w = ((const int4*)mask)[node * 64 + u];
            m0 = w.x; m1 = w.y; m2 = w.z; m3 = w.w;
        }
        unsigned nib = (m0 ? 1u : 0u) | (m1 ? 2u : 0u) | (m2 ? 4u : 0u) | (m3 ? 8u : 0u);
        unsigned v = nib << (4 * (t & 7));
        v |= __shfl_xor_sync(0xffffffffu, v, 1);
        v |= __shfl_xor_sync(0xffffffffu, v, 2);
        v |= __shfl_xor_sync(0xffffffffu, v, 4);
        if ((t & 7) == 0) g_mbits[node * 8 + (u >> 3)] = v;
        float4 xv = ((const float4*)x)[node * 64 + u];
        __half2 h01 = __floats2half2_rn(m0 ? 0.f : xv.x, m1 ? 0.f : xv.y);
        __half2 h23 = __floats2half2_rn(m2 ? 0.f : xv.z, m3 ? 0.f : xv.w);
        uint2 o;
        o.x = *(unsigned*)&h01;
        o.y = *(unsigned*)&h23;
        ((uint2*)g_x0h)[node * 64 + u] = o;
        return;
    }
    b -= PBLK;
    if (b < eb) {
        int i = b * 256 + t;
        if (i < E) {
            int dst = g_flags[1] ? (int)((const long long*)edges)[E + i]
                                 : ((const int*)edges)[E + i];
            atomicAdd(&g_count[dst], 1);
        }
        return;
    }
    b -= eb;
    if (b < 8 * 352) {
        // bprep
        int g = b / 352, n = b % 352;
        float val;
        if (n < 32) {
            val = W[t * FDIM + g * 32 + n];
        } else {
            int mat = (n - 32) >> 5;
            int o = g * 32 + ((n - 32) & 31);
            int k = mat >> 1;
            float w = W[t * FDIM + o];
            if ((mat & 1) == 0) val = means[k * FDIM + t] * w;
            else                val = expf(logvars[k * FDIM + t]) * w * w;
        }
        g_B[g][n * FDIM + t] = __float2half_rn(val);
        return;
    }
    b -= 8 * 352;
    if (b < 5) {
        int i = b * 256 + t;
        if (i < KMIX * FDIM) g_ivar[i] = expf(-logvars[i]);
        return;
    }
    b -= 5;
    {
        int i = b * 256 + t;
        if (i <= 1024) {
            float w0 = -8.0f + i * (1.0f / 64.0f);
            float h0 = h_exact(w0);
            float h1 = h_exact(w0 + (1.0f / 64.0f));
            g_htab[i] = make_float2(h0, h1 - h0);
        }
    }
}

// ---------------- parallel scan (2 small launches; offsets inline later)
__global__ __launch_bounds__(256) void scanA_kernel() {
    int b = blockIdx.x, t = threadIdx.x;
    int i = b * 256 + t;
    int v = (i < NNODES) ? g_count[i] : 0;
    __shared__ int sh[256];
    sh[t] = v;
    __syncthreads();
    for (int off = 1; off < 256; off <<= 1) {
        int u = (t >= off) ? sh[t - off] : 0;
        __syncthreads();
        sh[t] += u;
        __syncthreads();
    }
    if (i < NNODES) g_locs[i] = sh[t] - v;
    if (t == 255) g_bsum[b] = sh[255];
}

__global__ __launch_bounds__(256) void scanB_kernel() {
    int t = threadIdx.x;
    int v = (t < NBLK) ? g_bsum[t] : 0;
    __shared__ int sh[256];
    sh[t] = v;
    __syncthreads();
    for (int off = 1; off < 256; off <<= 1) {
        int u = (t >= off) ? sh[t - off] : 0;
        __syncthreads();
        sh[t] += u;
        __syncthreads();
    }
    if (t < NBLK) g_boff[t] = sh[t] - v;
    if (t == 255) g_boff[NBLK] = sh[255];
}

__device__ __forceinline__ int node_offset(int n) {
    return (n < NNODES) ? (g_locs[n] + g_boff[n >> 8]) : g_boff[NBLK];
}

// ---------------- scatter (offsets computed inline) ----------------
__global__ void scatter_kernel(const void* __restrict__ edges, int E) {
    int i = blockIdx.x * blockDim.x + threadIdx.x;
    if (i >= E) return;
    int src, dst;
    if (g_flags[1]) {
        const long long* e = (const long long*)edges;
        src = (int)e[i]; dst = (int)e[E + i];
    } else {
        const int* e = (const int*)edges;
        src = e[i]; dst = e[E + i];
    }
    int pos = atomicAdd(&g_cursor[dst], 1);
    g_sorted[g_locs[dst] + g_boff[dst >> 8] + pos] = src;
}

// ---------------- aggregate: 64 thr/node, 4 feat/thr, fp16 gather -------
__global__ __launch_bounds__(64) void aggregate_kernel(
    const float* __restrict__ x, const float* __restrict__ logp,
    const float* __restrict__ means)
{
    int n = blockIdx.x;
    int u = threadIdx.x;                   // 0..63, features 4u..4u+3
    int wsel = u >> 3, shift = 4 * (u & 7);

    int beg = node_offset(n), end = node_offset(n + 1);

    unsigned nib = (g_mbits[n * 8 + wsel] >> shift) & 0xfu;
    float4 xv = ((const float4*)x)[n * 64 + u];
    float acc0 = (nib & 1u) ? 0.f : xv.x;
    float acc1 = (nib & 2u) ? 0.f : xv.y;
    float acc2 = (nib & 4u) ? 0.f : xv.z;
    float acc3 = (nib & 8u) ? 0.f : xv.w;
    int cnt0 = nib & 1, cnt1 = (nib >> 1) & 1, cnt2 = (nib >> 2) & 1, cnt3 = (nib >> 3) & 1;

    // gamma logits partial (self x only)
    float q[KMIX];
#pragma unroll
    for (int k = 0; k < KMIX; k++) {
        float4 mk = ((const float4*)means)[k * 64 + u];
        float4 iv = ((const float4*)g_ivar)[k * 64 + u];
        float d0 = xv.x - mk.x, d1 = xv.y - mk.y, d2 = xv.z - mk.z, d3 = xv.w - mk.w;
        float s = 0.f;
        if (!(nib & 1u)) s += d0 * d0 * iv.x;
        if (!(nib & 2u)) s += d1 * d1 * iv.y;
        if (!(nib & 4u)) s += d2 * d2 * iv.z;
        if (!(nib & 8u)) s += d3 * d3 * iv.w;
        q[k] = s;
    }

    __shared__ int ssrc[64];
    const uint2* x0 = (const uint2*)g_x0h;
    for (int chunk = beg; chunk < end; chunk += 64) {
        int nload = min(64, end - chunk);
        __syncthreads();
        if (u < nload) ssrc[u] = g_sorted[chunk + u];
        __syncthreads();
        int i = 0;
        for (; i + 2 <= nload; i += 2) {
            int s0 = ssrc[i], s1 = ssrc[i + 1];
            uint2 w0 = __ldg(&x0[(size_t)s0 * 64 + u]);
            uint2 w1 = __ldg(&x0[(size_t)s1 * 64 + u]);
            unsigned nb0 = (__ldg(&g_mbits[s0 * 8 + wsel]) >> shift) & 0xfu;
            unsigned nb1 = (__ldg(&g_mbits[s1 * 8 + wsel]) >> shift) & 0xfu;
            float2 a01 = __half22float2(*(__half2*)&w0.x);
            float2 a23 = __half22float2(*(__half2*)&w0.y);
            float2 b01 = __half22float2(*(__half2*)&w1.x);
            float2 b23 = __half22float2(*(__half2*)&w1.y);
            acc0 += a01.x + b01.x;
            acc1 += a01.y + b01.y;
            acc2 += a23.x + b23.x;
            acc3 += a23.y + b23.y;
            cnt0 += (nb0 & 1) + (nb1 & 1);
            cnt1 += ((nb0 >> 1) & 1) + ((nb1 >> 1) & 1);
            cnt2 += ((nb0 >> 2) & 1) + ((nb1 >> 2) & 1);
            cnt3 += ((nb0 >> 3) & 1) + ((nb1 >> 3) & 1);
        }
        if (i < nload) {
            int s0 = ssrc[i];
            uint2 w0 = __ldg(&x0[(size_t)s0 * 64 + u]);
            unsigned nb0 = (__ldg(&g_mbits[s0 * 8 + wsel]) >> shift) & 0xfu;
            float2 a01 = __half22float2(*(__half2*)&w0.x);
            float2 a23 = __half22float2(*(__half2*)&w0.y);
            acc0 += a01.x; acc1 += a01.y; acc2 += a23.x; acc3 += a23.y;
            cnt0 += nb0 & 1; cnt1 += (nb0 >> 1) & 1;
            cnt2 += (nb0 >> 2) & 1; cnt3 += (nb0 >> 3) & 1;
        }
    }

    {
        __half2 h01 = __floats2half2_rn(acc0, acc1);
        __half2 h23 = __floats2half2_rn(acc2, acc3);
        uint2 o; o.x = *(unsigned*)&h01; o.y = *(unsigned*)&h23;
        ((uint2*)g_S0h)[n * 64 + u] = o;
        __half2 c01 = __floats2half2_rn((float)cnt0, (float)cnt1);
        __half2 c23 = __floats2half2_rn((float)cnt2, (float)cnt3);
        uint2 c; c.x = *(unsigned*)&c01; c.y = *(unsigned*)&c23;
        ((uint2*)g_SMh)[n * 64 + u] = c;
    }
    if (u == 0) g_indeg[n] = (float)(end - beg);

    // gamma reduction + softmax (64 threads = 2 warps)
#pragma unroll
    for (int k = 0; k < KMIX; k++)
        for (int off = 16; off; off >>= 1)
            q[k] += __shfl_down_sync(0xffffffffu, q[k], off);
    __shared__ float red[2][KMIX];
    if ((u & 31) == 0)
#pragma unroll
        for (int k = 0; k < KMIX; k++) red[u >> 5][k] = q[k];
    __syncthreads();
    if (u == 0) {
        float l[KMIX], mx = -1e30f;
#pragma unroll
        for (int k = 0; k < KMIX; k++) {
            l[k] = logp[k] - 0.5f * (red[0][k] + red[1][k]);
            mx = fmaxf(mx, l[k]);
        }
        float e[KMIX], se = 0.f;
#pragma unroll
        for (int k = 0; k < KMIX; k++) { e[k] = __expf(l[k] - mx); se += e[k]; }
        float inv = 1.0f / se;
#pragma unroll
        for (int k = 0; k < KMIX; k++) g_gamma[n * KMIX + k] = e[k] * inv;
    }
}

// ---------------- mma.sync GEMM + table epilogue ----------------
__device__ __forceinline__ float ex_relu_tab(float mu, float s, const float2* htab) {
    if (s <= 0.0f) return fmaxf(mu, 0.0f);
    float rs = rsqrtf(s);
    float w  = mu * rs;
    if (w >= 8.0f) return mu;
    if (w <= -8.0f) return 0.0f;
    float ss = s * rs;               // = sqrt(s)
    float p = (w + 8.0f) * 64.0f;
    int i = (int)p;
    float frac = p - (float)i;
    float2 e = htab[i];
    return ss * fmaf(frac, e.y, e.x);
}

// SMEM layout (per buffer), 80-byte row pitch (conflict-free ldmatrix)
#define OFF_A0H 0
#define OFF_AMH 5120
#define OFF_B   10240
#define BUFSZ   38400
#define OFF_HTAB (2 * BUFSZ)              // 76800
#define SM_TOTAL (2 * BUFSZ + 8224)       // 85024

__device__ __forceinline__ void load_chunk(uint32_t sbuf, int nb, int g, int kc) {
    int t = threadIdx.x;
    const char* srcA0 = (const char*)g_S0h;
    const char* srcA2 = (const char*)g_SMh;
#pragma unroll
    for (int j = 0; j < 2; j++) {
        int id = t + j * 256;                 // 512 total
        int tile = id >> 8, rem = id & 255;
        int row = rem >> 2, c16 = rem & 3;
        int node = nb + row; if (node >= NNODES) node = NNODES - 1;
        const char* base = tile == 0 ? srcA0 : srcA2;
        const char* src = base + ((size_t)node * FDIM + kc * 32 + c16 * 8) * 2;
        uint32_t dst = sbuf + OFF_A0H + tile * 5120 + row * 80 + c16 * 16;
        cpasync16(dst, src);
    }
    const char* bp = (const char*)&g_B[g][0];
#pragma unroll
    for (int j = 0; j < 6; j++) {
        int id = t + j * 256;                 // 1408 total
        if (id < 1408) {
            int row = id >> 2, c16 = id & 3;
            const char* src = bp + ((size_t)row * FDIM + kc * 32 + c16 * 8) * 2;
            uint32_t dst = sbuf + OFF_B + row * 80 + c16 * 16;
            cpasync16(dst, src);
        }
    }
}

__global__ __launch_bounds__(256, 2) void gemm_mma_kernel(
    const float* __restrict__ bias, float* __restrict__ out)
{
    extern __shared__ char smem[];
    uint32_t sb = smem_u32(smem);
    int t = threadIdx.x;
    int lane = t & 31, wid = t >> 5;
    int wm = wid & 3, wn = wid >> 2;          // 4 m-tiles x 2 n-tiles
    int nb = blockIdx.y * 64;                 // node tile
    int g  = blockIdx.x;                      // group — A reuse in-wave
    int ob = g * 32;

    // copy h-table into smem (ordered by the first __syncthreads below)
    float2* htab = (float2*)(smem + OFF_HTAB);
    for (int i = t; i < 1025; i += 256) htab[i] = g_htab[i];

    float acc[11][8];
#pragma unroll
    for (int a = 0; a < 11; a++)
#pragma unroll
        for (int d = 0; d < 8; d++) acc[a][d] = 0.0f;

    load_chunk(sb, nb, g, 0);
    CP_COMMIT();

    int arow = wm * 16 + (lane & 15);
    int acolsel = (lane >> 4) << 3;
    int brow = wn * 16 + (lane & 7) + ((lane >> 4) << 3);
    int bcolsel = ((lane >> 3) & 1) << 3;

    for (int c = 0; c < 8; c++) {
        if (c < 7) { load_chunk(sb + ((c + 1) & 1) * BUFSZ, nb, g, c + 1); CP_COMMIT(); CP_WAIT1(); }
        else CP_WAIT0();
        __syncthreads();

        uint32_t b32 = sb + (c & 1) * BUFSZ;
#pragma unroll
        for (int j = 0; j < 2; j++) {
            uint32_t aoff = (uint32_t)(arow * 80 + (j * 16 + acolsel) * 2);
            uint32_t aH[4], aM[4];
            ldsm4(aH, b32 + OFF_A0H + aoff);
            ldsm4(aM, b32 + OFF_AMH + aoff);

            uint32_t boff0 = (uint32_t)(brow * 80 + (j * 16 + bcolsel) * 2);
            uint32_t bq[4];
            // t0 path: S0h * B
            ldsm4(bq, b32 + OFF_B + boff0);
            mma16816(&acc[0][0], aH, &bq[0]); mma16816(&acc[0][4], aH, &bq[2]);
            // SM path: counts * B  (counts exact in fp16)
#pragma unroll
            for (int a = 1; a <= 10; a++) {
                uint32_t boff = boff0 + (uint32_t)(a * 32 * 80);
                ldsm4(bq, b32 + OFF_B + boff);
                mma16816(&acc[a][0], aM, &bq[0]); mma16816(&acc[a][4], aM, &bq[2]);
            }
        }
        __syncthreads();
    }

    int r0 = lane >> 2, c0 = (lane & 3) * 2;
#pragma unroll
    for (int i = 0; i < 2; i++) {
        int node = nb + wm * 16 + r0 + i * 8;
        if (node >= NNODES) continue;
        float deg1 = 1.0f + g_indeg[node];
        float gam[KMIX];
#pragma unroll
        for (int k = 0; k < KMIX; k++) gam[k] = g_gamma[node * KMIX + k];
#pragma unroll
        for (int f = 0; f < 2; f++) {
            int o = ob + wn * 16 + f * 8 + c0;
            float bb0 = bias[o] * deg1;
            float bb1 = bias[o + 1] * deg1;
            int d = f * 4 + i * 2;
            float mu0 = acc[0][d], mu1 = acc[0][d + 1];
            float s0 = 0.f, s1 = 0.f;
#pragma unroll
            for (int k = 0; k < KMIX; k++) {
                s0 += gam[k] * ex_relu_tab(mu0 + acc[1 + 2 * k][d] + bb0,     acc[2 + 2 * k][d],     htab);
                s1 += gam[k] * ex_relu_tab(mu1 + acc[1 + 2 * k][d + 1] + bb1, acc[2 + 2 * k][d + 1], htab);
            }
            *(float2*)&out[(size_t)node * FDIM + o] = make_float2(s0, s1);
        }
    }
}

// ---------------- launcher ----------------
extern "C" void kernel_launch(void* const* d_in, const int* in_sizes, int n_in,
                              void* d_out, int out_size) {
    const float* x       = (const float*)d_in[0];
    const void*  edges   = d_in[1];
    const void*  mask    = d_in[2];
    const float* logp    = (const float*)d_in[3];
    const float* means   = (const float*)d_in[4];
    const float* logvars = (const float*)d_in[5];
    const float* W       = (const float*)d_in[6];
    const float* bias    = (const float*)d_in[7];
    float* out = (float*)d_out;

    int E = in_sizes[1] / 2;
    int eb = (E + 255) / 256;

    cudaFuncSetAttribute(gemm_mma_kernel, cudaFuncAttributeMaxDynamicSharedMemorySize, SM_TOTAL);

    zero_detect_kernel<<<NBLK + 1, 256>>>(mask, edges);
    megaprep_kernel<<<PBLK + eb + 8 * 352 + 10, 256>>>(mask, edges, E, eb, x, W, means, logvars);
    scanA_kernel<<<NBLK, 256>>>();
    scanB_kernel<<<1, 256>>>();
    scatter_kernel<<<eb, 256>>>(edges, E);
    aggregate_kernel<<<NNODES, 64>>>(x, logp, means);

    dim3 ggrid(8, (NNODES + 63) / 64);
    gemm_mma_kernel<<<ggrid, 256, SM_TOTAL>>>(bias, out);
}

// round 14
// speedup vs baseline: 1.5748x; 1.0301x over previous
#include <cuda_runtime.h>
#include <cuda_fp16.h>
#include <cstdint>

#define NNODES 50000
#define FDIM   256
#define KMIX   5
#define EMAX   1700000
#define NBLK   196                          // ceil(NNODES/256)
#define PBLK   (NNODES / 4)                 // 12500 prep blocks (4 nodes each)

// ---------------- scratch ----------------
__device__ unsigned g_mbits[NNODES * 8];      // bit mask, 256 bits/node
__device__ float g_indeg[NNODES];
__device__ float g_gamma[NNODES * KMIX];
__device__ int   g_flags[2];
__device__ int   g_count[NNODES];
__device__ int   g_cursor[NNODES];
__device__ int   g_locs[NNODES];              // local exclusive scans
__device__ int   g_bsum[NBLK];
__device__ int   g_boff[NBLK + 1];
__device__ int   g_sorted[EMAX];
__device__ float g_ivar[KMIX * FDIM];         // exp(-logvars)
__device__ float2 g_htab[1025];               // h(w): value, delta-per-interval
__device__ __half g_x0h[NNODES * FDIM];       // fp16 masked x (gather source)
__device__ __half g_S0h[NNODES * FDIM];       // fp16 aggregated S0
__device__ __half g_SMh[NNODES * FDIM];       // aggregated mask counts (exact fp16)
// B concat (single fp16): [group g (32 outs)][352 rows (n)][256 (k)]
__device__ __half g_B[8][352 * 256];

// ---------------- PTX helpers (baseline ISA only) ----------------
__device__ __forceinline__ uint32_t smem_u32(const void* p) {
    uint32_t a;
    asm("{ .reg .u64 t; cvta.to.shared.u64 t, %1; cvt.u32.u64 %0, t; }" : "=r"(a) : "l"(p));
    return a;
}
__device__ __forceinline__ void cpasync16(uint32_t dst, const void* src) {
    asm volatile("cp.async.cg.shared.global [%0], [%1], 16;" :: "r"(dst), "l"(src));
}
#define CP_COMMIT() asm volatile("cp.async.commit_group;" ::: "memory")
#define CP_WAIT1()  asm volatile("cp.async.wait_group 1;" ::: "memory")
#define CP_WAIT0()  asm volatile("cp.async.wait_group 0;" ::: "memory")

__device__ __forceinline__ void ldsm4(uint32_t* r, uint32_t addr) {
    asm volatile("ldmatrix.sync.aligned.m8n8.x4.shared.b16 {%0,%1,%2,%3}, [%4];"
                 : "=r"(r[0]), "=r"(r[1]), "=r"(r[2]), "=r"(r[3]) : "r"(addr));
}
__device__ __forceinline__ void mma16816(float* d, const uint32_t* a, const uint32_t* b) {
    asm volatile("mma.sync.aligned.m16n8k16.row.col.f32.f16.f16.f32 "
                 "{%0,%1,%2,%3}, {%4,%5,%6,%7}, {%8,%9}, {%0,%1,%2,%3};"
                 : "+f"(d[0]), "+f"(d[1]), "+f"(d[2]), "+f"(d[3])
                 : "r"(a[0]), "r"(a[1]), "r"(a[2]), "r"(a[3]), "r"(b[0]), "r"(b[1]));
}

// ---------------- launch 1: zero counters + global dtype detect --------
__global__ void zero_detect_kernel(const void* mask, const void* edges) {
    int b = blockIdx.x, t = threadIdx.x;
    if (b < NBLK) {
        int i = b * 256 + t;
        if (i < NNODES) { g_count[i] = 0; g_cursor[i] = 0; }
    } else {
        int any_m = 0, any_e = 0;
        const unsigned char* mb = (const unsigned char*)mask;
        const int* ei = (const int*)edges;
        for (int i = t; i < 4096; i += 256) {
            if (mb[4 * i + 1] != 0) any_m = 1;
            if (ei[2 * i + 1] != 0) any_e = 1;
        }
        any_m = __syncthreads_or(any_m);
        any_e = __syncthreads_or(any_e);
        if (t == 0) { g_flags[0] = any_m ? 1 : 0; g_flags[1] = any_e ? 0 : 1; }
    }
}

// ---------------- launch 2: megaprep = prep+x0h + count + bprep + ivar + htab
__device__ __forceinline__ float h_exact(float w) {
    return 0.3989422804014327f * expf(-0.5f * w * w)
         + 0.5f * w * (1.0f + erff(w * 0.7071067811865476f));
}

__global__ __launch_bounds__(256) void megaprep_kernel(
    const void* __restrict__ mask, const void* __restrict__ edges, int E, int eb,
    const float* __restrict__ x,
    const float* __restrict__ W, const float* __restrict__ means,
    const float* __restrict__ logvars)
{
    int b = blockIdx.x, t = threadIdx.x;
    if (b < PBLK) {
        // prep: 4 nodes/block, 64 threads/node, 4 features/thread
        int node = b * 4 + (t >> 6);
        int u = t & 63;
        int m0, m1, m2, m3;
        if (g_flags[0]) {
            uchar4 w = ((const uchar4*)mask)[node * 64 + u];
            m0 = w.x; m1 = w.y; m2 = w.z; m3 = w.w;
        } else {
            int4 w = ((const int4*)mask)[node * 64 + u];
            m0 = w.x; m1 = w.y; m2 = w.z; m3 = w.w;
        }
        unsigned nib = (m0 ? 1u : 0u) | (m1 ? 2u : 0u) | (m2 ? 4u : 0u) | (m3 ? 8u : 0u);
        unsigned v = nib << (4 * (t & 7));
        v |= __shfl_xor_sync(0xffffffffu, v, 1);
        v |= __shfl_xor_sync(0xffffffffu, v, 2);
        v |= __shfl_xor_sync(0xffffffffu, v, 4);
        if ((t & 7) == 0) g_mbits[node * 8 + (u >> 3)] = v;
        float4 xv = ((const float4*)x)[node * 64 + u];
        __half2 h01 = __floats2half2_rn(m0 ? 0.f : xv.x, m1 ? 0.f : xv.y);
        __half2 h23 = __floats2half2_rn(m2 ? 0.f : xv.z, m3 ? 0.f : xv.w);
        uint2 o;
        o.x = *(unsigned*)&h01;
        o.y = *(unsigned*)&h23;
        ((uint2*)g_x0h)[node * 64 + u] = o;
        return;
    }
    b -= PBLK;
    if (b < eb) {
        int i = b * 256 + t;
        if (i < E) {
            int dst = g_flags[1] ? (int)((const long long*)edges)[E + i]
                                 : ((const int*)edges)[E + i];
            atomicAdd(&g_count[dst], 1);
        }
        return;
    }
    b -= eb;
    if (b < 8 * 352) {
        // bprep
        int g = b / 352, n = b % 352;
        float val;
        if (n < 32) {
            val = W[t * FDIM + g * 32 + n];
        } else {
            int mat = (n - 32) >> 5;
            int o = g * 32 + ((n - 32) & 31);
            int k = mat >> 1;
            float w = W[t * FDIM + o];
            if ((mat & 1) == 0) val = means[k * FDIM + t] * w;
            else                val = expf(logvars[k * FDIM + t]) * w * w;
        }
        g_B[g][n * FDIM + t] = __float2half_rn(val);
        return;
    }
    b -= 8 * 352;
    if (b < 5) {
        int i = b * 256 + t;
        if (i < KMIX * FDIM) g_ivar[i] = expf(-logvars[i]);
        return;
    }
    b -= 5;
    {
        int i = b * 256 + t;
        if (i <= 1024) {
            float w0 = -8.0f + i * (1.0f / 64.0f);
            float h0 = h_exact(w0);
            float h1 = h_exact(w0 + (1.0f / 64.0f));
            g_htab[i] = make_float2(h0, h1 - h0);
        }
    }
}

// ---------------- parallel scan (2 small launches; offsets inline later)
__global__ __launch_bounds__(256) void scanA_kernel() {
    int b = blockIdx.x, t = threadIdx.x;
    int i = b * 256 + t;
    int v = (i < NNODES) ? g_count[i] : 0;
    __shared__ int sh[256];
    sh[t] = v;
    __syncthreads();
    for (int off = 1; off < 256; off <<= 1) {
        int u = (t >= off) ? sh[t - off] : 0;
        __syncthreads();
        sh[t] += u;
        __syncthreads();
    }
    if (i < NNODES) g_locs[i] = sh[t] - v;
    if (t == 255) g_bsum[b] = sh[255];
}

__global__ __launch_bounds__(256) void scanB_kernel() {
    int t = threadIdx.x;
    int v = (t < NBLK) ? g_bsum[t] : 0;
    __shared__ int sh[256];
    sh[t] = v;
    __syncthreads();
    for (int off = 1; off < 256; off <<= 1) {
        int u = (t >= off) ? sh[t - off] : 0;
        __syncthreads();
        sh[t] += u;
        __syncthreads();
    }
    if (t < NBLK) g_boff[t] = sh[t] - v;
    if (t == 255) g_boff[NBLK] = sh[255];
}

__device__ __forceinline__ int node_offset(int n) {
    return (n < NNODES) ? (g_locs[n] + g_boff[n >> 8]) : g_boff[NBLK];
}

// ---------------- scatter (offsets computed inline) ----------------
__global__ void scatter_kernel(const void* __restrict__ edges, int E) {
    int i = blockIdx.x * blockDim.x + threadIdx.x;
    if (i >= E) return;
    int src, dst;
    if (g_flags[1]) {
        const long long* e = (const long long*)edges;
        src = (int)e[i]; dst = (int)e[E + i];
    } else {
        const int* e = (const int*)edges;
        src = e[i]; dst = e[E + i];
    }
    int pos = atomicAdd(&g_cursor[dst], 1);
    g_sorted[g_locs[dst] + g_boff[dst >> 8] + pos] = src;
}

// ---------------- aggregate: 64 thr/node, 4 feat/thr, fp16 gather -------
__global__ __launch_bounds__(64) void aggregate_kernel(
    const float* __restrict__ x, const float* __restrict__ logp,
    const float* __restrict__ means)
{
    int n = blockIdx.x;
    int u = threadIdx.x;                   // 0..63, features 4u..4u+3
    int wsel = u >> 3, shift = 4 * (u & 7);

    int beg = node_offset(n), end = node_offset(n + 1);

    unsigned nib = (g_mbits[n * 8 + wsel] >> shift) & 0xfu;
    float4 xv = ((const float4*)x)[n * 64 + u];
    float acc0 = (nib & 1u) ? 0.f : xv.x;
    float acc1 = (nib & 2u) ? 0.f : xv.y;
    float acc2 = (nib & 4u) ? 0.f : xv.z;
    float acc3 = (nib & 8u) ? 0.f : xv.w;
    int cnt0 = nib & 1, cnt1 = (nib >> 1) & 1, cnt2 = (nib >> 2) & 1, cnt3 = (nib >> 3) & 1;

    // gamma logits partial (self x only)
    float q[KMIX];
#pragma unroll
    for (int k = 0; k < KMIX; k++) {
        float4 mk = ((const float4*)means)[k * 64 + u];
        float4 iv = ((const float4*)g_ivar)[k * 64 + u];
        float d0 = xv.x - mk.x, d1 = xv.y - mk.y, d2 = xv.z - mk.z, d3 = xv.w - mk.w;
        float s = 0.f;
        if (!(nib & 1u)) s += d0 * d0 * iv.x;
        if (!(nib & 2u)) s += d1 * d1 * iv.y;
        if (!(nib & 4u)) s += d2 * d2 * iv.z;
        if (!(nib & 8u)) s += d3 * d3 * iv.w;
        q[k] = s;
    }

    __shared__ int ssrc[64];
    const uint2* x0 = (const uint2*)g_x0h;
    for (int chunk = beg; chunk < end; chunk += 64) {
        int nload = min(64, end - chunk);
        __syncthreads();
        if (u < nload) ssrc[u] = g_sorted[chunk + u];
        __syncthreads();
        int i = 0;
        for (; i + 2 <= nload; i += 2) {
            int s0 = ssrc[i], s1 = ssrc[i + 1];
            uint2 w0 = __ldg(&x0[(size_t)s0 * 64 + u]);
            uint2 w1 = __ldg(&x0[(size_t)s1 * 64 + u]);
            unsigned nb0 = (__ldg(&g_mbits[s0 * 8 + wsel]) >> shift) & 0xfu;
            unsigned nb1 = (__ldg(&g_mbits[s1 * 8 + wsel]) >> shift) & 0xfu;
            float2 a01 = __half22float2(*(__half2*)&w0.x);
            float2 a23 = __half22float2(*(__half2*)&w0.y);
            float2 b01 = __half22float2(*(__half2*)&w1.x);
            float2 b23 = __half22float2(*(__half2*)&w1.y);
            acc0 += a01.x + b01.x;
            acc1 += a01.y + b01.y;
            acc2 += a23.x + b23.x;
            acc3 += a23.y + b23.y;
            cnt0 += (nb0 & 1) + (nb1 & 1);
            cnt1 += ((nb0 >> 1) & 1) + ((nb1 >> 1) & 1);
            cnt2 += ((nb0 >> 2) & 1) + ((nb1 >> 2) & 1);
            cnt3 += ((nb0 >> 3) & 1) + ((nb1 >> 3) & 1);
        }
        if (i < nload) {
            int s0 = ssrc[i];
            uint2 w0 = __ldg(&x0[(size_t)s0 * 64 + u]);
            unsigned nb0 = (__ldg(&g_mbits[s0 * 8 + wsel]) >> shift) & 0xfu;
            float2 a01 = __half22float2(*(__half2*)&w0.x);
            float2 a23 = __half22float2(*(__half2*)&w0.y);
            acc0 += a01.x; acc1 += a01.y; acc2 += a23.x; acc3 += a23.y;
            cnt0 += nb0 & 1; cnt1 += (nb0 >> 1) & 1;
            cnt2 += (nb0 >> 2) & 1; cnt3 += (nb0 >> 3) & 1;
        }
    }

    {
        __half2 h01 = __floats2half2_rn(acc0, acc1);
        __half2 h23 = __floats2half2_rn(acc2, acc3);
        uint2 o; o.x = *(unsigned*)&h01; o.y = *(unsigned*)&h23;
        ((uint2*)g_S0h)[n * 64 + u] = o;
        __half2 c01 = __floats2half2_rn((float)cnt0, (float)cnt1);
        __half2 c23 = __floats2half2_rn((float)cnt2, (float)cnt3);
        uint2 c; c.x = *(unsigned*)&c01; c.y = *(unsigned*)&c23;
        ((uint2*)g_SMh)[n * 64 + u] = c;
    }
    if (u == 0) g_indeg[n] = (float)(end - beg);

    // gamma reduction + softmax (64 threads = 2 warps)
#pragma unroll
    for (int k = 0; k < KMIX; k++)
        for (int off = 16; off; off >>= 1)
            q[k] += __shfl_down_sync(0xffffffffu, q[k], off);
    __shared__ float red[2][KMIX];
    if ((u & 31) == 0)
#pragma unroll
        for (int k = 0; k < KMIX; k++) red[u >> 5][k] = q[k];
    __syncthreads();
    if (u == 0) {
        float l[KMIX], mx = -1e30f;
#pragma unroll
        for (int k = 0; k < KMIX; k++) {
            l[k] = logp[k] - 0.5f * (red[0][k] + red[1][k]);
            mx = fmaxf(mx, l[k]);
        }
        float e[KMIX], se = 0.f;
#pragma unroll
        for (int k = 0; k < KMIX; k++) { e[k] = __expf(l[k] - mx); se += e[k]; }
        float inv = 1.0f / se;
#pragma unroll
        for (int k = 0; k < KMIX; k++) g_gamma[n * KMIX + k] = e[k] * inv;
    }
}

// ---------------- mma.sync GEMM (128-node tile) + table epilogue --------
__device__ __forceinline__ float ex_relu_tab(float mu, float s, const float2* htab) {
    if (s <= 0.0f) return fmaxf(mu, 0.0f);
    float rs = rsqrtf(s);
    float w  = mu * rs;
    if (w >= 8.0f) return mu;
    if (w <= -8.0f) return 0.0f;
    float ss = s * rs;               // = sqrt(s)
    float p = (w + 8.0f) * 64.0f;
    int i = (int)p;
    float frac = p - (float)i;
    float2 e = htab[i];
    return ss * fmaf(frac, e.y, e.x);
}

// SMEM layout (per buffer), 80-byte row pitch (conflict-free ldmatrix)
#define OFF_A0H 0
#define OFF_AMH 10240
#define OFF_B   20480
#define BUFSZ   48640
#define OFF_HTAB (2 * BUFSZ)              // 97280
#define SM_TOTAL (2 * BUFSZ + 8224)       // 105504

__device__ __forceinline__ void load_chunk(uint32_t sbuf, int nb, int g, int kc) {
    int t = threadIdx.x;                   // 512 threads
    const char* srcA0 = (const char*)g_S0h;
    const char* srcA2 = (const char*)g_SMh;
#pragma unroll
    for (int j = 0; j < 2; j++) {
        int id = t + j * 512;                 // 1024 total (2 tiles x 128 rows x 4)
        int tile = id >> 9, rem = id & 511;
        int row = rem >> 2, c16 = rem & 3;
        int node = nb + row; if (node >= NNODES) node = NNODES - 1;
        const char* base = tile == 0 ? srcA0 : srcA2;
        const char* src = base + ((size_t)node * FDIM + kc * 32 + c16 * 8) * 2;
        uint32_t dst = sbuf + OFF_A0H + tile * 10240 + row * 80 + c16 * 16;
        cpasync16(dst, src);
    }
    const char* bp = (const char*)&g_B[g][0];
#pragma unroll
    for (int j = 0; j < 3; j++) {
        int id = t + j * 512;                 // 1408 total
        if (id < 1408) {
            int row = id >> 2, c16 = id & 3;
            const char* src = bp + ((size_t)row * FDIM + kc * 32 + c16 * 8) * 2;
            uint32_t dst = sbuf + OFF_B + row * 80 + c16 * 16;
            cpasync16(dst, src);
        }
    }
}

__global__ __launch_bounds__(512, 1) void gemm_mma_kernel(
    const float* __restrict__ bias, float* __restrict__ out)
{
    extern __shared__ char smem[];
    uint32_t sb = smem_u32(smem);
    int t = threadIdx.x;
    int lane = t & 31, wid = t >> 5;
    int wm = wid & 7, wn = wid >> 3;          // 8 m-tiles x 2 n-tiles
    int nb = blockIdx.y * 128;                // node tile (128 nodes)
    int g  = blockIdx.x;                      // group — A reuse in-wave
    int ob = g * 32;

    // copy h-table into smem (ordered by the first __syncthreads below)
    float2* htab = (float2*)(smem + OFF_HTAB);
    for (int i = t; i < 1025; i += 512) htab[i] = g_htab[i];

    float acc[11][8];
#pragma unroll
    for (int a = 0; a < 11; a++)
#pragma unroll
        for (int d = 0; d < 8; d++) acc[a][d] = 0.0f;

    load_chunk(sb, nb, g, 0);
    CP_COMMIT();

    int arow = wm * 16 + (lane & 15);
    int acolsel = (lane >> 4) << 3;
    int brow = wn * 16 + (lane & 7) + ((lane >> 4) << 3);
    int bcolsel = ((lane >> 3) & 1) << 3;

    for (int c = 0; c < 8; c++) {
        if (c < 7) { load_chunk(sb + ((c + 1) & 1) * BUFSZ, nb, g, c + 1); CP_COMMIT(); CP_WAIT1(); }
        else CP_WAIT0();
        __syncthreads();

        uint32_t b32 = sb + (c & 1) * BUFSZ;
#pragma unroll
        for (int j = 0; j < 2; j++) {
            uint32_t aoff = (uint32_t)(arow * 80 + (j * 16 + acolsel) * 2);
            uint32_t aH[4], aM[4];
            ldsm4(aH, b32 + OFF_A0H + aoff);
            ldsm4(aM, b32 + OFF_AMH + aoff);

            uint32_t boff0 = (uint32_t)(brow * 80 + (j * 16 + bcolsel) * 2);
            uint32_t bq[4];
            // t0 path: S0h * B
            ldsm4(bq, b32 + OFF_B + boff0);
            mma16816(&acc[0][0], aH, &bq[0]); mma16816(&acc[0][4], aH, &bq[2]);
            // SM path: counts * B  (counts exact in fp16)
#pragma unroll
            for (int a = 1; a <= 10; a++) {
                uint32_t boff = boff0 + (uint32_t)(a * 32 * 80);
                ldsm4(bq, b32 + OFF_B + boff);
                mma16816(&acc[a][0], aM, &bq[0]); mma16816(&acc[a][4], aM, &bq[2]);
            }
        }
        __syncthreads();
    }

    int r0 = lane >> 2, c0 = (lane & 3) * 2;
#pragma unroll
    for (int i = 0; i < 2; i++) {
        int node = nb + wm * 16 + r0 + i * 8;
        if (node >= NNODES) continue;
        float deg1 = 1.0f + g_indeg[node];
        float gam[KMIX];
#pragma unroll
        for (int k = 0; k < KMIX; k++) gam[k] = g_gamma[node * KMIX + k];
#pragma unroll
        for (int f = 0; f < 2; f++) {
            int o = ob + wn * 16 + f * 8 + c0;
            float bb0 = bias[o] * deg1;
            float bb1 = bias[o + 1] * deg1;
            int d = f * 4 + i * 2;
            float mu0 = acc[0][d], mu1 = acc[0][d + 1];
            float s0 = 0.f, s1 = 0.f;
#pragma unroll
            for (int k = 0; k < KMIX; k++) {
                s0 += gam[k] * ex_relu_tab(mu0 + acc[1 + 2 * k][d] + bb0,     acc[2 + 2 * k][d],     htab);
                s1 += gam[k] * ex_relu_tab(mu1 + acc[1 + 2 * k][d + 1] + bb1, acc[2 + 2 * k][d + 1], htab);
            }
            *(float2*)&out[(size_t)node * FDIM + o] = make_float2(s0, s1);
        }
    }
}

// ---------------- launcher ----------------
extern "C" void kernel_launch(void* const* d_in, const int* in_sizes, int n_in,
                              void* d_out, int out_size) {
    const float* x       = (const float*)d_in[0];
    const void*  edges   = d_in[1];
    const void*  mask    = d_in[2];
    const float* logp    = (const float*)d_in[3];
    const float* means   = (const float*)d_in[4];
    const float* logvars = (const float*)d_in[5];
    const float* W       = (const float*)d_in[6];
    const float* bias    = (const float*)d_in[7];
    float* out = (float*)d_out;

    int E = in_sizes[1] / 2;
    int eb = (E + 255) / 256;

    cudaFuncSetAttribute(gemm_mma_kernel, cudaFuncAttributeMaxDynamicSharedMemorySize, SM_TOTAL);

    zero_detect_kernel<<<NBLK + 1, 256>>>(mask, edges);
    megaprep_kernel<<<PBLK + eb + 8 * 352 + 10, 256>>>(mask, edges, E, eb, x, W, means, logvars);
    scanA_kernel<<<NBLK, 256>>>();
    scanB_kernel<<<1, 256>>>();
    scatter_kernel<<<eb, 256>>>(edges, E);
    aggregate_kernel<<<NNODES, 64>>>(x, logp, means);

    dim3 ggrid(8, (NNODES + 127) / 128);
    gemm_mma_kernel<<<ggrid, 512, SM_TOTAL>>>(bias, out);
}

// round 15
// speedup vs baseline: 1.6083x; 1.0212x over previous
#include <cuda_runtime.h>
#include <cuda_fp16.h>
#include <cstdint>

#define NNODES 50000
#define FDIM   256
#define KMIX   5
#define EMAX   1700000
#define NBLK   196                          // ceil(NNODES/256)
#define PBLK   (NNODES / 4)                 // 12500 prep blocks (4 nodes each)

// ---------------- scratch ----------------
__device__ unsigned g_mbits[NNODES * 8];      // bit mask, 256 bits/node
__device__ float g_indeg[NNODES];
__device__ float g_gamma[NNODES * KMIX];
__device__ int   g_flags[2];
__device__ int   g_count[NNODES];
__device__ int   g_cursor[NNODES];
__device__ int   g_locs[NNODES];              // local exclusive scans
__device__ int   g_bsum[NBLK];
__device__ int   g_boff[NBLK + 1];
__device__ int   g_sorted[EMAX];
__device__ float g_ivar[KMIX * FDIM];         // exp(-logvars)
__device__ float2 g_htab[1025];               // h(w): value, delta-per-interval
__device__ __half g_x0h[NNODES * FDIM];       // fp16 masked x (gather source)
__device__ __half g_S0h[NNODES * FDIM];       // fp16 aggregated S0
__device__ __half g_SMh[NNODES * FDIM];       // aggregated mask counts (exact fp16)
// B concat (single fp16): [group g (32 outs)][352 rows (n)][256 (k)]
__device__ __half g_B[8][352 * 256];

// ---------------- PTX helpers (baseline ISA only) ----------------
__device__ __forceinline__ uint32_t smem_u32(const void* p) {
    uint32_t a;
    asm("{ .reg .u64 t; cvta.to.shared.u64 t, %1; cvt.u32.u64 %0, t; }" : "=r"(a) : "l"(p));
    return a;
}
__device__ __forceinline__ void cpasync16(uint32_t dst, const void* src) {
    asm volatile("cp.async.cg.shared.global [%0], [%1], 16;" :: "r"(dst), "l"(src));
}
#define CP_COMMIT() asm volatile("cp.async.commit_group;" ::: "memory")
#define CP_WAIT1()  asm volatile("cp.async.wait_group 1;" ::: "memory")
#define CP_WAIT0()  asm volatile("cp.async.wait_group 0;" ::: "memory")

__device__ __forceinline__ void ldsm4(uint32_t* r, uint32_t addr) {
    asm volatile("ldmatrix.sync.aligned.m8n8.x4.shared.b16 {%0,%1,%2,%3}, [%4];"
                 : "=r"(r[0]), "=r"(r[1]), "=r"(r[2]), "=r"(r[3]) : "r"(addr));
}
__device__ __forceinline__ void mma16816(float* d, const uint32_t* a, const uint32_t* b) {
    asm volatile("mma.sync.aligned.m16n8k16.row.col.f32.f16.f16.f32 "
                 "{%0,%1,%2,%3}, {%4,%5,%6,%7}, {%8,%9}, {%0,%1,%2,%3};"
                 : "+f"(d[0]), "+f"(d[1]), "+f"(d[2]), "+f"(d[3])
                 : "r"(a[0]), "r"(a[1]), "r"(a[2]), "r"(a[3]), "r"(b[0]), "r"(b[1]));
}

// ---------------- launch 1: zero counters + global dtype detect --------
__global__ void zero_detect_kernel(const void* mask, const void* edges) {
    int b = blockIdx.x, t = threadIdx.x;
    if (b < NBLK) {
        int i = b * 256 + t;
        if (i < NNODES) { g_count[i] = 0; g_cursor[i] = 0; }
    } else {
        int any_m = 0, any_e = 0;
        const unsigned char* mb = (const unsigned char*)mask;
        const int* ei = (const int*)edges;
        for (int i = t; i < 4096; i += 256) {
            if (mb[4 * i + 1] != 0) any_m = 1;
            if (ei[2 * i + 1] != 0) any_e = 1;
        }
        any_m = __syncthreads_or(any_m);
        any_e = __syncthreads_or(any_e);
        if (t == 0) { g_flags[0] = any_m ? 1 : 0; g_flags[1] = any_e ? 0 : 1; }
    }
}

// ---------------- launch 2: megaprep = prep+x0h + count + bprep + ivar + htab
__device__ __forceinline__ float h_exact(float w) {
    return 0.3989422804014327f * expf(-0.5f * w * w)
         + 0.5f * w * (1.0f + erff(w * 0.7071067811865476f));
}

__global__ __launch_bounds__(256) void megaprep_kernel(
    const void* __restrict__ mask, const void* __restrict__ edges, int E, int eb,
    const float* __restrict__ x,
    const float* __restrict__ W, const float* __restrict__ means,
    const float* __restrict__ logvars)
{
    int b = blockIdx.x, t = threadIdx.x;
    if (b < PBLK) {
        // prep: 4 nodes/block, 64 threads/node, 4 features/thread
        int node = b * 4 + (t >> 6);
        int u = t & 63;
        int m0, m1, m2, m3;
        if (g_flags[0]) {
            uchar4 w = ((const uchar4*)mask)[node * 64 + u];
            m0 = w.x; m1 = w.y; m2 = w.z; m3 = w.w;
        } else {
            int4 w = ((const int4*)mask)[node * 64 + u];
            m0 = w.x; m1 = w.y; m2 = w.z; m3 = w.w;
        }
        unsigned nib = (m0 ? 1u : 0u) | (m1 ? 2u : 0u) | (m2 ? 4u : 0u) | (m3 ? 8u : 0u);
        unsigned v = nib << (4 * (t & 7));
        v |= __shfl_xor_sync(0xffffffffu, v, 1);
        v |= __shfl_xor_sync(0xffffffffu, v, 2);
        v |= __shfl_xor_sync(0xffffffffu, v, 4);
        if ((t & 7) == 0) g_mbits[node * 8 + (u >> 3)] = v;
        float4 xv = ((const float4*)x)[node * 64 + u];
        __half2 h01 = __floats2half2_rn(m0 ? 0.f : xv.x, m1 ? 0.f : xv.y);
        __half2 h23 = __floats2half2_rn(m2 ? 0.f : xv.z, m3 ? 0.f : xv.w);
        uint2 o;
        o.x = *(unsigned*)&h01;
        o.y = *(unsigned*)&h23;
        ((uint2*)g_x0h)[node * 64 + u] = o;
        return;
    }
    b -= PBLK;
    if (b < eb) {
        int i = b * 256 + t;
        if (i < E) {
            int dst = g_flags[1] ? (int)((const long long*)edges)[E + i]
                                 : ((const int*)edges)[E + i];
            atomicAdd(&g_count[dst], 1);
        }
        return;
    }
    b -= eb;
    if (b < 8 * 352) {
        // bprep
        int g = b / 352, n = b % 352;
        float val;
        if (n < 32) {
            val = W[t * FDIM + g * 32 + n];
        } else {
            int mat = (n - 32) >> 5;
            int o = g * 32 + ((n - 32) & 31);
            int k = mat >> 1;
            float w = W[t * FDIM + o];
            if ((mat & 1) == 0) val = means[k * FDIM + t] * w;
            else                val = expf(logvars[k * FDIM + t]) * w * w;
        }
        g_B[g][n * FDIM + t] = __float2half_rn(val);
        return;
    }
    b -= 8 * 352;
    if (b < 5) {
        int i = b * 256 + t;
        if (i < KMIX * FDIM) g_ivar[i] = expf(-logvars[i]);
        return;
    }
    b -= 5;
    {
        int i = b * 256 + t;
        if (i <= 1024) {
            float w0 = -8.0f + i * (1.0f / 64.0f);
            float h0 = h_exact(w0);
            float h1 = h_exact(w0 + (1.0f / 64.0f));
            g_htab[i] = make_float2(h0, h1 - h0);
        }
    }
}

// ---------------- parallel scan (2 small launches; offsets inline later)
__global__ __launch_bounds__(256) void scanA_kernel() {
    int b = blockIdx.x, t = threadIdx.x;
    int i = b * 256 + t;
    int v = (i < NNODES) ? g_count[i] : 0;
    __shared__ int sh[256];
    sh[t] = v;
    __syncthreads();
    for (int off = 1; off < 256; off <<= 1) {
        int u = (t >= off) ? sh[t - off] : 0;
        __syncthreads();
        sh[t] += u;
        __syncthreads();
    }
    if (i < NNODES) g_locs[i] = sh[t] - v;
    if (t == 255) g_bsum[b] = sh[255];
}

__global__ __launch_bounds__(256) void scanB_kernel() {
    int t = threadIdx.x;
    int v = (t < NBLK) ? g_bsum[t] : 0;
    __shared__ int sh[256];
    sh[t] = v;
    __syncthreads();
    for (int off = 1; off < 256; off <<= 1) {
        int u = (t >= off) ? sh[t - off] : 0;
        __syncthreads();
        sh[t] += u;
        __syncthreads();
    }
    if (t < NBLK) g_boff[t] = sh[t] - v;
    if (t == 255) g_boff[NBLK] = sh[255];
}

__device__ __forceinline__ int node_offset(int n) {
    return (n < NNODES) ? (g_locs[n] + g_boff[n >> 8]) : g_boff[NBLK];
}

// ---------------- scatter (offsets computed inline) ----------------
__global__ void scatter_kernel(const void* __restrict__ edges, int E) {
    int i = blockIdx.x * blockDim.x + threadIdx.x;
    if (i >= E) return;
    int src, dst;
    if (g_flags[1]) {
        const long long* e = (const long long*)edges;
        src = (int)e[i]; dst = (int)e[E + i];
    } else {
        const int* e = (const int*)edges;
        src = e[i]; dst = e[E + i];
    }
    int pos = atomicAdd(&g_cursor[dst], 1);
    g_sorted[g_locs[dst] + g_boff[dst >> 8] + pos] = src;
}

// ---------------- aggregate: 64 thr/node, 4 feat/thr, fp16 gather -------
__global__ __launch_bounds__(64) void aggregate_kernel(
    const float* __restrict__ x, const float* __restrict__ logp,
    const float* __restrict__ means)
{
    int n = blockIdx.x;
    int u = threadIdx.x;                   // 0..63, features 4u..4u+3
    int wsel = u >> 3, shift = 4 * (u & 7);

    int beg = node_offset(n), end = node_offset(n + 1);

    unsigned nib = (g_mbits[n * 8 + wsel] >> shift) & 0xfu;
    float4 xv = ((const float4*)x)[n * 64 + u];
    float acc0 = (nib & 1u) ? 0.f : xv.x;
    float acc1 = (nib & 2u) ? 0.f : xv.y;
    float acc2 = (nib & 4u) ? 0.f : xv.z;
    float acc3 = (nib & 8u) ? 0.f : xv.w;
    int cnt0 = nib & 1, cnt1 = (nib >> 1) & 1, cnt2 = (nib >> 2) & 1, cnt3 = (nib >> 3) & 1;

    // gamma logits partial (self x only)
    float q[KMIX];
#pragma unroll
    for (int k = 0; k < KMIX; k++) {
        float4 mk = ((const float4*)means)[k * 64 + u];
        float4 iv = ((const float4*)g_ivar)[k * 64 + u];
        float d0 = xv.x - mk.x, d1 = xv.y - mk.y, d2 = xv.z - mk.z, d3 = xv.w - mk.w;
        float s = 0.f;
        if (!(nib & 1u)) s += d0 * d0 * iv.x;
        if (!(nib & 2u)) s += d1 * d1 * iv.y;
        if (!(nib & 4u)) s += d2 * d2 * iv.z;
        if (!(nib & 8u)) s += d3 * d3 * iv.w;
        q[k] = s;
    }

    __shared__ int ssrc[64];
    const uint2* x0 = (const uint2*)g_x0h;
    for (int chunk = beg; chunk < end; chunk += 64) {
        int nload = min(64, end - chunk);
        __syncthreads();
        if (u < nload) ssrc[u] = g_sorted[chunk + u];
        __syncthreads();
        int i = 0;
        for (; i + 2 <= nload; i += 2) {
            int s0 = ssrc[i], s1 = ssrc[i + 1];
            uint2 w0 = __ldg(&x0[(size_t)s0 * 64 + u]);
            uint2 w1 = __ldg(&x0[(size_t)s1 * 64 + u]);
            unsigned nb0 = (__ldg(&g_mbits[s0 * 8 + wsel]) >> shift) & 0xfu;
            unsigned nb1 = (__ldg(&g_mbits[s1 * 8 + wsel]) >> shift) & 0xfu;
            float2 a01 = __half22float2(*(__half2*)&w0.x);
            float2 a23 = __half22float2(*(__half2*)&w0.y);
            float2 b01 = __half22float2(*(__half2*)&w1.x);
            float2 b23 = __half22float2(*(__half2*)&w1.y);
            acc0 += a01.x + b01.x;
            acc1 += a01.y + b01.y;
            acc2 += a23.x + b23.x;
            acc3 += a23.y + b23.y;
            cnt0 += (nb0 & 1) + (nb1 & 1);
            cnt1 += ((nb0 >> 1) & 1) + ((nb1 >> 1) & 1);
            cnt2 += ((nb0 >> 2) & 1) + ((nb1 >> 2) & 1);
            cnt3 += ((nb0 >> 3) & 1) + ((nb1 >> 3) & 1);
        }
        if (i < nload) {
            int s0 = ssrc[i];
            uint2 w0 = __ldg(&x0[(size_t)s0 * 64 + u]);
            unsigned nb0 = (__ldg(&g_mbits[s0 * 8 + wsel]) >> shift) & 0xfu;
            float2 a01 = __half22float2(*(__half2*)&w0.x);
            float2 a23 = __half22float2(*(__half2*)&w0.y);
            acc0 += a01.x; acc1 += a01.y; acc2 += a23.x; acc3 += a23.y;
            cnt0 += nb0 & 1; cnt1 += (nb0 >> 1) & 1;
            cnt2 += (nb0 >> 2) & 1; cnt3 += (nb0 >> 3) & 1;
        }
    }

    {
        __half2 h01 = __floats2half2_rn(acc0, acc1);
        __half2 h23 = __floats2half2_rn(acc2, acc3);
        uint2 o; o.x = *(unsigned*)&h01; o.y = *(unsigned*)&h23;
        ((uint2*)g_S0h)[n * 64 + u] = o;
        __half2 c01 = __floats2half2_rn((float)cnt0, (float)cnt1);
        __half2 c23 = __floats2half2_rn((float)cnt2, (float)cnt3);
        uint2 c; c.x = *(unsigned*)&c01; c.y = *(unsigned*)&c23;
        ((uint2*)g_SMh)[n * 64 + u] = c;
    }
    if (u == 0) g_indeg[n] = (float)(end - beg);

    // gamma reduction + softmax (64 threads = 2 warps)
#pragma unroll
    for (int k = 0; k < KMIX; k++)
        for (int off = 16; off; off >>= 1)
            q[k] += __shfl_down_sync(0xffffffffu, q[k], off);
    __shared__ float red[2][KMIX];
    if ((u & 31) == 0)
#pragma unroll
        for (int k = 0; k < KMIX; k++) red[u >> 5][k] = q[k];
    __syncthreads();
    if (u == 0) {
        float l[KMIX], mx = -1e30f;
#pragma unroll
        for (int k = 0; k < KMIX; k++) {
            l[k] = logp[k] - 0.5f * (red[0][k] + red[1][k]);
            mx = fmaxf(mx, l[k]);
        }
        float e[KMIX], se = 0.f;
#pragma unroll
        for (int k = 0; k < KMIX; k++) { e[k] = __expf(l[k] - mx); se += e[k]; }
        float inv = 1.0f / se;
#pragma unroll
        for (int k = 0; k < KMIX; k++) g_gamma[n * KMIX + k] = e[k] * inv;
    }
}

// ---------------- mma.sync GEMM (128-node tile, K64 chunks) -------------
__device__ __forceinline__ float ex_relu_tab(float mu, float s, const float2* htab) {
    if (s <= 0.0f) return fmaxf(mu, 0.0f);
    float rs = rsqrtf(s);
    float w  = mu * rs;
    if (w >= 8.0f) return mu;
    if (w <= -8.0f) return 0.0f;
    float ss = s * rs;               // = sqrt(s)
    float p = (w + 8.0f) * 64.0f;
    int i = (int)p;
    float frac = p - (float)i;
    float2 e = htab[i];
    return ss * fmaf(frac, e.y, e.x);
}

// SMEM layout (per buffer), 144-byte row pitch (64 halfs + pad; 144/16=9 odd -> conflict-free ldsm)
#define PITCH   144
#define OFF_A0H 0
#define OFF_AMH (128 * PITCH)             // 18432
#define OFF_B   (2 * 128 * PITCH)         // 36864
#define BUFSZ   (2 * 128 * PITCH + 352 * PITCH)   // 87552
#define OFF_HTAB (2 * BUFSZ)              // 175104
#define SM_TOTAL (2 * BUFSZ + 8224)       // 183328

__device__ __forceinline__ void load_chunk(uint32_t sbuf, int nb, int g, int kc) {
    int t = threadIdx.x;                   // 512 threads
    const char* srcA0 = (const char*)g_S0h;
    const char* srcA2 = (const char*)g_SMh;
    const char* bp = (const char*)&g_B[g][0];
    // A: 2 tiles x 128 rows x 8 c16 = 2048; B: 352 x 8 = 2816; total 4864
    for (int id = t; id < 4864; id += 512) {
        if (id < 2048) {
            int tile = id >> 10, rem = id & 1023;
            int row = rem >> 3, c16 = rem & 7;
            int node = nb + row; if (node >= NNODES) node = NNODES - 1;
            const char* base = tile == 0 ? srcA0 : srcA2;
            const char* src = base + ((size_t)node * FDIM + kc * 64 + c16 * 8) * 2;
            uint32_t dst = sbuf + OFF_A0H + tile * (128 * PITCH) + row * PITCH + c16 * 16;
            cpasync16(dst, src);
        } else {
            int rem = id - 2048;
            int row = rem >> 3, c16 = rem & 7;
            const char* src = bp + ((size_t)row * FDIM + kc * 64 + c16 * 8) * 2;
            uint32_t dst = sbuf + OFF_B + row * PITCH + c16 * 16;
            cpasync16(dst, src);
        }
    }
}

__global__ __launch_bounds__(512, 1) void gemm_mma_kernel(
    const float* __restrict__ bias, float* __restrict__ out)
{
    extern __shared__ char smem[];
    uint32_t sb = smem_u32(smem);
    int t = threadIdx.x;
    int lane = t & 31, wid = t >> 5;
    int wm = wid & 7, wn = wid >> 3;          // 8 m-tiles x 2 n-tiles
    int nb = blockIdx.y * 128;                // node tile (128 nodes)
    int g  = blockIdx.x;                      // group — A reuse in-wave
    int ob = g * 32;

    // copy h-table into smem (ordered by the first __syncthreads below)
    float2* htab = (float2*)(smem + OFF_HTAB);
    for (int i = t; i < 1025; i += 512) htab[i] = g_htab[i];

    float acc[11][8];
#pragma unroll
    for (int a = 0; a < 11; a++)
#pragma unroll
        for (int d = 0; d < 8; d++) acc[a][d] = 0.0f;

    load_chunk(sb, nb, g, 0);
    CP_COMMIT();

    int arow = wm * 16 + (lane & 15);
    int acolsel = (lane >> 4) << 3;
    int brow = wn * 16 + (lane & 7) + ((lane >> 4) << 3);
    int bcolsel = ((lane >> 3) & 1) << 3;

    for (int c = 0; c < 4; c++) {
        if (c < 3) { load_chunk(sb + ((c + 1) & 1) * BUFSZ, nb, g, c + 1); CP_COMMIT(); CP_WAIT1(); }
        else CP_WAIT0();
        __syncthreads();

        uint32_t b32 = sb + (c & 1) * BUFSZ;
#pragma unroll
        for (int j = 0; j < 4; j++) {
            uint32_t aoff = (uint32_t)(arow * PITCH + (j * 16 + acolsel) * 2);
            uint32_t aH[4], aM[4];
            ldsm4(aH, b32 + OFF_A0H + aoff);
            ldsm4(aM, b32 + OFF_AMH + aoff);

            uint32_t boff0 = (uint32_t)(brow * PITCH + (j * 16 + bcolsel) * 2);
            uint32_t bq[4];
            // t0 path: S0h * B
            ldsm4(bq, b32 + OFF_B + boff0);
            mma16816(&acc[0][0], aH, &bq[0]); mma16816(&acc[0][4], aH, &bq[2]);
            // SM path: counts * B  (counts exact in fp16)
#pragma unroll
            for (int a = 1; a <= 10; a++) {
                uint32_t boff = boff0 + (uint32_t)(a * 32 * PITCH);
                ldsm4(bq, b32 + OFF_B + boff);
                mma16816(&acc[a][0], aM, &bq[0]); mma16816(&acc[a][4], aM, &bq[2]);
            }
        }
        __syncthreads();
    }

    int r0 = lane >> 2, c0 = (lane & 3) * 2;
#pragma unroll
    for (int i = 0; i < 2; i++) {
        int node = nb + wm * 16 + r0 + i * 8;
        if (node >= NNODES) continue;
        float deg1 = 1.0f + g_indeg[node];
        float gam[KMIX];
#pragma unroll
        for (int k = 0; k < KMIX; k++) gam[k] = g_gamma[node * KMIX + k];
#pragma unroll
        for (int f = 0; f < 2; f++) {
            int o = ob + wn * 16 + f * 8 + c0;
            float bb0 = bias[o] * deg1;
            float bb1 = bias[o + 1] * deg1;
            int d = f * 4 + i * 2;
            float mu0 = acc[0][d], mu1 = acc[0][d + 1];
            float s0 = 0.f, s1 = 0.f;
#pragma unroll
            for (int k = 0; k < KMIX; k++) {
                s0 += gam[k] * ex_relu_tab(mu0 + acc[1 + 2 * k][d] + bb0,     acc[2 + 2 * k][d],     htab);
                s1 += gam[k] * ex_relu_tab(mu1 + acc[1 + 2 * k][d + 1] + bb1, acc[2 + 2 * k][d + 1], htab);
            }
            *(float2*)&out[(size_t)node * FDIM + o] = make_float2(s0, s1);
        }
    }
}

// ---------------- launcher ----------------
extern "C" void kernel_launch(void* const* d_in, const int* in_sizes, int n_in,
                              void* d_out, int out_size) {
    const float* x       = (const float*)d_in[0];
    const void*  edges   = d_in[1];
    const void*  mask    = d_in[2];
    const float* logp    = (const float*)d_in[3];
    const float* means   = (const float*)d_in[4];
    const float* logvars = (const float*)d_in[5];
    const float* W       = (const float*)d_in[6];
    const float* bias    = (const float*)d_in[7];
    float* out = (float*)d_out;

    int E = in_sizes[1] / 2;
    int eb = (E + 255) / 256;

    cudaFuncSetAttribute(gemm_mma_kernel, cudaFuncAttributeMaxDynamicSharedMemorySize, SM_TOTAL);

    zero_detect_kernel<<<NBLK + 1, 256>>>(mask, edges);
    megaprep_kernel<<<PBLK + eb + 8 * 352 + 10, 256>>>(mask, edges, E, eb, x, W, means, logvars);
    scanA_kernel<<<NBLK, 256>>>();
    scanB_kernel<<<1, 256>>>();
    scatter_kernel<<<eb, 256>>>(edges, E);
    aggregate_kernel<<<NNODES, 64>>>(x, logp, means);

    dim3 ggrid(8, (NNODES + 127) / 128);
    gemm_mma_kernel<<<ggrid, 512, SM_TOTAL>>>(bias, out);
}

// round 16
// speedup vs baseline: 1.6945x; 1.0536x over previous
#include <cuda_runtime.h>
#include <cuda_fp16.h>
#include <cstdint>

#define NNODES 50000
#define FDIM   256
#define KMIX   5
#define EMAX   1700000
#define NBLK   196                          // ceil(NNODES/256)
#define PBLK   (NNODES / 4)                 // 12500 prep blocks (4 nodes each)

// ---------------- scratch ----------------
__device__ unsigned g_mbits[NNODES * 8];      // bit mask, 256 bits/node
__device__ float g_indeg[NNODES];
__device__ float g_gamma[NNODES * KMIX];
__device__ int   g_flags[2];
__device__ int   g_count[NNODES];
__device__ int   g_cursor[NNODES];
__device__ int   g_locs[NNODES];              // local exclusive scans
__device__ int   g_bsum[NBLK];
__device__ int   g_boff[NBLK + 1];
__device__ int   g_sorted[EMAX];
__device__ float g_ivar[KMIX * FDIM];         // exp(-logvars)
__device__ float2 g_htab[1025];               // h(w): value, delta-per-interval
__device__ __half g_x0h[NNODES * FDIM];       // fp16 masked x (gather source)
__device__ __half g_S0h[NNODES * FDIM];       // fp16 aggregated S0
__device__ __half g_SMh[NNODES * FDIM];       // aggregated mask counts (exact fp16)
// B concat (single fp16): [group g (32 outs)][352 rows (n)][256 (k)]
__device__ __half g_B[8][352 * 256];

// ---------------- PTX helpers (baseline ISA only) ----------------
__device__ __forceinline__ uint32_t smem_u32(const void* p) {
    uint32_t a;
    asm("{ .reg .u64 t; cvta.to.shared.u64 t, %1; cvt.u32.u64 %0, t; }" : "=r"(a) : "l"(p));
    return a;
}
__device__ __forceinline__ void cpasync16(uint32_t dst, const void* src) {
    asm volatile("cp.async.cg.shared.global [%0], [%1], 16;" :: "r"(dst), "l"(src));
}
#define CP_COMMIT() asm volatile("cp.async.commit_group;" ::: "memory")
#define CP_WAIT1()  asm volatile("cp.async.wait_group 1;" ::: "memory")
#define CP_WAIT0()  asm volatile("cp.async.wait_group 0;" ::: "memory")

__device__ __forceinline__ void ldsm4(uint32_t* r, uint32_t addr) {
    asm volatile("ldmatrix.sync.aligned.m8n8.x4.shared.b16 {%0,%1,%2,%3}, [%4];"
                 : "=r"(r[0]), "=r"(r[1]), "=r"(r[2]), "=r"(r[3]) : "r"(addr));
}
__device__ __forceinline__ void mma16816(float* d, const uint32_t* a, const uint32_t* b) {
    asm volatile("mma.sync.aligned.m16n8k16.row.col.f32.f16.f16.f32 "
                 "{%0,%1,%2,%3}, {%4,%5,%6,%7}, {%8,%9}, {%0,%1,%2,%3};"
                 : "+f"(d[0]), "+f"(d[1]), "+f"(d[2]), "+f"(d[3])
                 : "r"(a[0]), "r"(a[1]), "r"(a[2]), "r"(a[3]), "r"(b[0]), "r"(b[1]));
}

// ---------------- launch 1: zero counters + global dtype detect --------
__global__ void zero_detect_kernel(const void* mask, const void* edges) {
    int b = blockIdx.x, t = threadIdx.x;
    if (b < NBLK) {
        int i = b * 256 + t;
        if (i < NNODES) { g_count[i] = 0; g_cursor[i] = 0; }
    } else {
        int any_m = 0, any_e = 0;
        const unsigned char* mb = (const unsigned char*)mask;
        const int* ei = (const int*)edges;
        for (int i = t; i < 4096; i += 256) {
            if (mb[4 * i + 1] != 0) any_m = 1;
            if (ei[2 * i + 1] != 0) any_e = 1;
        }
        any_m = __syncthreads_or(any_m);
        any_e = __syncthreads_or(any_e);
        if (t == 0) { g_flags[0] = any_m ? 1 : 0; g_flags[1] = any_e ? 0 : 1; }
    }
}

// ---------------- launch 2: megaprep = prep+x0h + count + bprep + ivar + htab
__device__ __forceinline__ float h_exact(float w) {
    return 0.3989422804014327f * expf(-0.5f * w * w)
         + 0.5f * w * (1.0f + erff(w * 0.7071067811865476f));
}

__global__ __launch_bounds__(256) void megaprep_kernel(
    const void* __restrict__ mask, const void* __restrict__ edges, int E, int eb,
    const float* __restrict__ x,
    const float* __restrict__ W, const float* __restrict__ means,
    const float* __restrict__ logvars)
{
    int b = blockIdx.x, t = threadIdx.x;
    if (b < PBLK) {
        // prep: 4 nodes/block, 64 threads/node, 4 features/thread
        int node = b * 4 + (t >> 6);
        int u = t & 63;
        int m0, m1, m2, m3;
        if (g_flags[0]) {
            uchar4 w = ((const uchar4*)mask)[node * 64 + u];
            m0 = w.x; m1 = w.y; m2 = w.z; m3 = w.w;
        } else {
            int4 w = ((const int4*)mask)[node * 64 + u];
            m0 = w.x; m1 = w.y; m2 = w.z; m3 = w.w;
        }
        unsigned nib = (m0 ? 1u : 0u) | (m1 ? 2u : 0u) | (m2 ? 4u : 0u) | (m3 ? 8u : 0u);
        unsigned v = nib << (4 * (t & 7));
        v |= __shfl_xor_sync(0xffffffffu, v, 1);
        v |= __shfl_xor_sync(0xffffffffu, v, 2);
        v |= __shfl_xor_sync(0xffffffffu, v, 4);
        if ((t & 7) == 0) g_mbits[node * 8 + (u >> 3)] = v;
        float4 xv = ((const float4*)x)[node * 64 + u];
        __half2 h01 = __floats2half2_rn(m0 ? 0.f : xv.x, m1 ? 0.f : xv.y);
        __half2 h23 = __floats2half2_rn(m2 ? 0.f : xv.z, m3 ? 0.f : xv.w);
        uint2 o;
        o.x = *(unsigned*)&h01;
        o.y = *(unsigned*)&h23;
        ((uint2*)g_x0h)[node * 64 + u] = o;
        return;
    }
    b -= PBLK;
    if (b < eb) {
        int i = b * 256 + t;
        if (i < E) {
            int dst = g_flags[1] ? (int)((const long long*)edges)[E + i]
                                 : ((const int*)edges)[E + i];
            atomicAdd(&g_count[dst], 1);
        }
        return;
    }
    b -= eb;
    if (b < 8 * 352) {
        // bprep
        int g = b / 352, n = b % 352;
        float val;
        if (n < 32) {
            val = W[t * FDIM + g * 32 + n];
        } else {
            int mat = (n - 32) >> 5;
            int o = g * 32 + ((n - 32) & 31);
            int k = mat >> 1;
            float w = W[t * FDIM + o];
            if ((mat & 1) == 0) val = means[k * FDIM + t] * w;
            else                val = expf(logvars[k * FDIM + t]) * w * w;
        }
        g_B[g][n * FDIM + t] = __float2half_rn(val);
        return;
    }
    b -= 8 * 352;
    if (b < 5) {
        int i = b * 256 + t;
        if (i < KMIX * FDIM) g_ivar[i] = expf(-logvars[i]);
        return;
    }
    b -= 5;
    {
        int i = b * 256 + t;
        if (i <= 1024) {
            float w0 = -8.0f + i * (1.0f / 64.0f);
            float h0 = h_exact(w0);
            float h1 = h_exact(w0 + (1.0f / 64.0f));
            g_htab[i] = make_float2(h0, h1 - h0);
        }
    }
}

// ---------------- parallel scan (2 small launches; offsets inline later)
__global__ __launch_bounds__(256) void scanA_kernel() {
    int b = blockIdx.x, t = threadIdx.x;
    int i = b * 256 + t;
    int v = (i < NNODES) ? g_count[i] : 0;
    __shared__ int sh[256];
    sh[t] = v;
    __syncthreads();
    for (int off = 1; off < 256; off <<= 1) {
        int u = (t >= off) ? sh[t - off] : 0;
        __syncthreads();
        sh[t] += u;
        __syncthreads();
    }
    if (i < NNODES) g_locs[i] = sh[t] - v;
    if (t == 255) g_bsum[b] = sh[255];
}

__global__ __launch_bounds__(256) void scanB_kernel() {
    int t = threadIdx.x;
    int v = (t < NBLK) ? g_bsum[t] : 0;
    __shared__ int sh[256];
    sh[t] = v;
    __syncthreads();
    for (int off = 1; off < 256; off <<= 1) {
        int u = (t >= off) ? sh[t - off] : 0;
        __syncthreads();
        sh[t] += u;
        __syncthreads();
    }
    if (t < NBLK) g_boff[t] = sh[t] - v;
    if (t == 255) g_boff[NBLK] = sh[255];
}

__device__ __forceinline__ int node_offset(int n) {
    return (n < NNODES) ? (g_locs[n] + g_boff[n >> 8]) : g_boff[NBLK];
}

// ---------------- scatter (offsets computed inline) ----------------
__global__ void scatter_kernel(const void* __restrict__ edges, int E) {
    int i = blockIdx.x * blockDim.x + threadIdx.x;
    if (i >= E) return;
    int src, dst;
    if (g_flags[1]) {
        const long long* e = (const long long*)edges;
        src = (int)e[i]; dst = (int)e[E + i];
    } else {
        const int* e = (const int*)edges;
        src = e[i]; dst = e[E + i];
    }
    int pos = atomicAdd(&g_cursor[dst], 1);
    g_sorted[g_locs[dst] + g_boff[dst >> 8] + pos] = src;
}

// ---------------- aggregate: 1 warp/node, 8 feat/thr, uint4 gather ------
__global__ __launch_bounds__(32) void aggregate_kernel(
    const float* __restrict__ x, const float* __restrict__ logp,
    const float* __restrict__ means)
{
    int n = blockIdx.x;
    int u = threadIdx.x;                   // 0..31, features 8u..8u+7
    int wsel = u >> 2;                     // mbits word
    int shift = 8 * (u & 3);               // byte within word

    int beg = node_offset(n), end = node_offset(n + 1);

    unsigned byte = (g_mbits[n * 8 + wsel] >> shift) & 0xffu;
    float4 xa = ((const float4*)x)[n * 64 + 2 * u];
    float4 xb = ((const float4*)x)[n * 64 + 2 * u + 1];
    float xs[8] = { xa.x, xa.y, xa.z, xa.w, xb.x, xb.y, xb.z, xb.w };

    float acc[8];
    int cnt[8];
#pragma unroll
    for (int j = 0; j < 8; j++) {
        int bj = (byte >> j) & 1;
        acc[j] = bj ? 0.f : xs[j];
        cnt[j] = bj;
    }

    // gamma logits partial (self x only)
    float q[KMIX];
#pragma unroll
    for (int k = 0; k < KMIX; k++) {
        float4 ma = ((const float4*)means)[k * 64 + 2 * u];
        float4 mb2 = ((const float4*)means)[k * 64 + 2 * u + 1];
        float4 ia = ((const float4*)g_ivar)[k * 64 + 2 * u];
        float4 ib = ((const float4*)g_ivar)[k * 64 + 2 * u + 1];
        float mk[8] = { ma.x, ma.y, ma.z, ma.w, mb2.x, mb2.y, mb2.z, mb2.w };
        float iv[8] = { ia.x, ia.y, ia.z, ia.w, ib.x, ib.y, ib.z, ib.w };
        float s = 0.f;
#pragma unroll
        for (int j = 0; j < 8; j++) {
            float d = xs[j] - mk[j];
            if (!((byte >> j) & 1)) s += d * d * iv[j];
        }
        q[k] = s;
    }

    __shared__ int ssrc[32];
    const uint4* x0 = (const uint4*)g_x0h;     // 32 uint4 per node row
    for (int chunk = beg; chunk < end; chunk += 32) {
        int nload = min(32, end - chunk);
        __syncwarp();
        if (u < nload) ssrc[u] = g_sorted[chunk + u];
        __syncwarp();
        int i = 0;
        for (; i + 2 <= nload; i += 2) {
            int s0 = ssrc[i], s1 = ssrc[i + 1];
            uint4 w0 = __ldg(&x0[(size_t)s0 * 32 + u]);
            uint4 w1 = __ldg(&x0[(size_t)s1 * 32 + u]);
            unsigned b0 = (__ldg(&g_mbits[s0 * 8 + wsel]) >> shift) & 0xffu;
            unsigned b1 = (__ldg(&g_mbits[s1 * 8 + wsel]) >> shift) & 0xffu;
            float2 a0 = __half22float2(*(__half2*)&w0.x);
            float2 a1 = __half22float2(*(__half2*)&w0.y);
            float2 a2 = __half22float2(*(__half2*)&w0.z);
            float2 a3 = __half22float2(*(__half2*)&w0.w);
            float2 c0 = __half22float2(*(__half2*)&w1.x);
            float2 c1 = __half22float2(*(__half2*)&w1.y);
            float2 c2 = __half22float2(*(__half2*)&w1.z);
            float2 c3 = __half22float2(*(__half2*)&w1.w);
            acc[0] += a0.x + c0.x;  acc[1] += a0.y + c0.y;
            acc[2] += a1.x + c1.x;  acc[3] += a1.y + c1.y;
            acc[4] += a2.x + c2.x;  acc[5] += a2.y + c2.y;
            acc[6] += a3.x + c3.x;  acc[7] += a3.y + c3.y;
#pragma unroll
            for (int j = 0; j < 8; j++)
                cnt[j] += ((b0 >> j) & 1) + ((b1 >> j) & 1);
        }
        if (i < nload) {
            int s0 = ssrc[i];
            uint4 w0 = __ldg(&x0[(size_t)s0 * 32 + u]);
            unsigned b0 = (__ldg(&g_mbits[s0 * 8 + wsel]) >> shift) & 0xffu;
            float2 a0 = __half22float2(*(__half2*)&w0.x);
            float2 a1 = __half22float2(*(__half2*)&w0.y);
            float2 a2 = __half22float2(*(__half2*)&w0.z);
            float2 a3 = __half22float2(*(__half2*)&w0.w);
            acc[0] += a0.x;  acc[1] += a0.y;
            acc[2] += a1.x;  acc[3] += a1.y;
            acc[4] += a2.x;  acc[5] += a2.y;
            acc[6] += a3.x;  acc[7] += a3.y;
#pragma unroll
            for (int j = 0; j < 8; j++) cnt[j] += (b0 >> j) & 1;
        }
    }

    {
        __half2 h0 = __floats2half2_rn(acc[0], acc[1]);
        __half2 h1 = __floats2half2_rn(acc[2], acc[3]);
        __half2 h2 = __floats2half2_rn(acc[4], acc[5]);
        __half2 h3 = __floats2half2_rn(acc[6], acc[7]);
        uint4 o;
        o.x = *(unsigned*)&h0; o.y = *(unsigned*)&h1;
        o.z = *(unsigned*)&h2; o.w = *(unsigned*)&h3;
        ((uint4*)g_S0h)[n * 32 + u] = o;
        __half2 c0 = __floats2half2_rn((float)cnt[0], (float)cnt[1]);
        __half2 c1 = __floats2half2_rn((float)cnt[2], (float)cnt[3]);
        __half2 c2 = __floats2half2_rn((float)cnt[4], (float)cnt[5]);
        __half2 c3 = __floats2half2_rn((float)cnt[6], (float)cnt[7]);
        uint4 c;
        c.x = *(unsigned*)&c0; c.y = *(unsigned*)&c1;
        c.z = *(unsigned*)&c2; c.w = *(unsigned*)&c3;
        ((uint4*)g_SMh)[n * 32 + u] = c;
    }
    if (u == 0) g_indeg[n] = (float)(end - beg);

    // gamma reduction + softmax (single warp)
#pragma unroll
    for (int k = 0; k < KMIX; k++)
        for (int off = 16; off; off >>= 1)
            q[k] += __shfl_down_sync(0xffffffffu, q[k], off);
    if (u == 0) {
        float l[KMIX], mx = -1e30f;
#pragma unroll
        for (int k = 0; k < KMIX; k++) {
            l[k] = logp[k] - 0.5f * q[k];
            mx = fmaxf(mx, l[k]);
        }
        float e[KMIX], se = 0.f;
#pragma unroll
        for (int k = 0; k < KMIX; k++) { e[k] = __expf(l[k] - mx); se += e[k]; }
        float inv = 1.0f / se;
#pragma unroll
        for (int k = 0; k < KMIX; k++) g_gamma[n * KMIX + k] = e[k] * inv;
    }
}

// ---------------- mma.sync GEMM (128-node tile, K64 chunks) -------------
__device__ __forceinline__ float ex_relu_tab(float mu, float s, const float2* htab) {
    if (s <= 0.0f) return fmaxf(mu, 0.0f);
    float rs = rsqrtf(s);
    float w  = mu * rs;
    if (w >= 8.0f) return mu;
    if (w <= -8.0f) return 0.0f;
    float ss = s * rs;               // = sqrt(s)
    float p = (w + 8.0f) * 64.0f;
    int i = (int)p;
    float frac = p - (float)i;
    float2 e = htab[i];
    return ss * fmaf(frac, e.y, e.x);
}

// SMEM layout (per buffer), 144-byte row pitch (64 halfs + pad; 144/16=9 odd -> conflict-free ldsm)
#define PITCH   144
#define OFF_A0H 0
#define OFF_AMH (128 * PITCH)             // 18432
#define OFF_B   (2 * 128 * PITCH)         // 36864
#define BUFSZ   (2 * 128 * PITCH + 352 * PITCH)   // 87552
#define OFF_HTAB (2 * BUFSZ)              // 175104
#define SM_TOTAL (2 * BUFSZ + 8224)       // 183328

__device__ __forceinline__ void load_chunk(uint32_t sbuf, int nb, int g, int kc) {
    int t = threadIdx.x;                   // 512 threads
    const char* srcA0 = (const char*)g_S0h;
    const char* srcA2 = (const char*)g_SMh;
    const char* bp = (const char*)&g_B[g][0];
    // A: 2 tiles x 128 rows x 8 c16 = 2048; B: 352 x 8 = 2816; total 4864
    for (int id = t; id < 4864; id += 512) {
        if (id < 2048) {
            int tile = id >> 10, rem = id & 1023;
            int row = rem >> 3, c16 = rem & 7;
            int node = nb + row; if (node >= NNODES) node = NNODES - 1;
            const char* base = tile == 0 ? srcA0 : srcA2;
            const char* src = base + ((size_t)node * FDIM + kc * 64 + c16 * 8) * 2;
            uint32_t dst = sbuf + OFF_A0H + tile * (128 * PITCH) + row * PITCH + c16 * 16;
            cpasync16(dst, src);
        } else {
            int rem = id - 2048;
            int row = rem >> 3, c16 = rem & 7;
            const char* src = bp + ((size_t)row * FDIM + kc * 64 + c16 * 8) * 2;
            uint32_t dst = sbuf + OFF_B + row * PITCH + c16 * 16;
            cpasync16(dst, src);
        }
    }
}

__global__ __launch_bounds__(512, 1) void gemm_mma_kernel(
    const float* __restrict__ bias, float* __restrict__ out)
{
    extern __shared__ char smem[];
    uint32_t sb = smem_u32(smem);
    int t = threadIdx.x;
    int lane = t & 31, wid = t >> 5;
    int wm = wid & 7, wn = wid >> 3;          // 8 m-tiles x 2 n-tiles
    int nb = blockIdx.y * 128;                // node tile (128 nodes)
    int g  = blockIdx.x;                      // group — A reuse in-wave
    int ob = g * 32;

    // copy h-table into smem (ordered by the first __syncthreads below)
    float2* htab = (float2*)(smem + OFF_HTAB);
    for (int i = t; i < 1025; i += 512) htab[i] = g_htab[i];

    float acc[11][8];
#pragma unroll
    for (int a = 0; a < 11; a++)
#pragma unroll
        for (int d = 0; d < 8; d++) acc[a][d] = 0.0f;

    load_chunk(sb, nb, g, 0);
    CP_COMMIT();

    int arow = wm * 16 + (lane & 15);
    int acolsel = (lane >> 4) << 3;
    int brow = wn * 16 + (lane & 7) + ((lane >> 4) << 3);
    int bcolsel = ((lane >> 3) & 1) << 3;

    for (int c = 0; c < 4; c++) {
        if (c < 3) { load_chunk(sb + ((c + 1) & 1) * BUFSZ, nb, g, c + 1); CP_COMMIT(); CP_WAIT1(); }
        else CP_WAIT0();
        __syncthreads();

        uint32_t b32 = sb + (c & 1) * BUFSZ;
#pragma unroll
        for (int j = 0; j < 4; j++) {
            uint32_t aoff = (uint32_t)(arow * PITCH + (j * 16 + acolsel) * 2);
            uint32_t aH[4], aM[4];
            ldsm4(aH, b32 + OFF_A0H + aoff);
            ldsm4(aM, b32 + OFF_AMH + aoff);

            uint32_t boff0 = (uint32_t)(brow * PITCH + (j * 16 + bcolsel) * 2);
            uint32_t bq[4];
            // t0 path: S0h * B
            ldsm4(bq, b32 + OFF_B + boff0);
            mma16816(&acc[0][0], aH, &bq[0]); mma16816(&acc[0][4], aH, &bq[2]);
            // SM path: counts * B  (counts exact in fp16)
#pragma unroll
            for (int a = 1; a <= 10; a++) {
                uint32_t boff = boff0 + (uint32_t)(a * 32 * PITCH);
                ldsm4(bq, b32 + OFF_B + boff);
                mma16816(&acc[a][0], aM, &bq[0]); mma16816(&acc[a][4], aM, &bq[2]);
            }
        }
        __syncthreads();
    }

    int r0 = lane >> 2, c0 = (lane & 3) * 2;
#pragma unroll
    for (int i = 0; i < 2; i++) {
        int node = nb + wm * 16 + r0 + i * 8;
        if (node >= NNODES) continue;
        float deg1 = 1.0f + g_indeg[node];
        float gam[KMIX];
#pragma unroll
        for (int k = 0; k < KMIX; k++) gam[k] = g_gamma[node * KMIX + k];
#pragma unroll
        for (int f = 0; f < 2; f++) {
            int o = ob + wn * 16 + f * 8 + c0;
            float bb0 = bias[o] * deg1;
            float bb1 = bias[o + 1] * deg1;
            int d = f * 4 + i * 2;
            float mu0 = acc[0][d], mu1 = acc[0][d + 1];
            float s0 = 0.f, s1 = 0.f;
#pragma unroll
            for (int k = 0; k < KMIX; k++) {
                s0 += gam[k] * ex_relu_tab(mu0 + acc[1 + 2 * k][d] + bb0,     acc[2 + 2 * k][d],     htab);
                s1 += gam[k] * ex_relu_tab(mu1 + acc[1 + 2 * k][d + 1] + bb1, acc[2 + 2 * k][d + 1], htab);
            }
            *(float2*)&out[(size_t)node * FDIM + o] = make_float2(s0, s1);
        }
    }
}

// ---------------- launcher ----------------
extern "C" void kernel_launch(void* const* d_in, const int* in_sizes, int n_in,
                              void* d_out, int out_size) {
    const float* x       = (const float*)d_in[0];
    const void*  edges   = d_in[1];
    const void*  mask    = d_in[2];
    const float* logp    = (const float*)d_in[3];
    const float* means   = (const float*)d_in[4];
    const float* logvars = (const float*)d_in[5];
    const float* W       = (const float*)d_in[6];
    const float* bias    = (const float*)d_in[7];
    float* out = (float*)d_out;

    int E = in_sizes[1] / 2;
    int eb = (E + 255) / 256;

    cudaFuncSetAttribute(gemm_mma_kernel, cudaFuncAttributeMaxDynamicSharedMemorySize, SM_TOTAL);

    zero_detect_kernel<<<NBLK + 1, 256>>>(mask, edges);
    megaprep_kernel<<<PBLK + eb + 8 * 352 + 10, 256>>>(mask, edges, E, eb, x, W, means, logvars);
    scanA_kernel<<<NBLK, 256>>>();
    scanB_kernel<<<1, 256>>>();
    scatter_kernel<<<eb, 256>>>(edges, E);
    aggregate_kernel<<<NNODES, 32>>>(x, logp, means);

    dim3 ggrid(8, (NNODES + 127) / 128);
    gemm_mma_kernel<<<ggrid, 512, SM_TOTAL>>>(bias, out);
}